// round 1
// baseline (speedup 1.0000x reference)
#include <cuda_runtime.h>
#include <math.h>

// ---------------- problem constants ----------------
#define Sq   2048   // sequence length (B=1)
#define Dm   2048   // model dim
#define Hn   16     // query heads
#define KVn  4      // kv heads
#define DHd  128    // head dim
#define En   8      // experts
#define Id   1024   // expert intermediate
#define HD   2048   // Hn*DHd
#define KVD  512    // KVn*DHd
#define EPSf 1e-6f

// ---------------- static device scratch ----------------
__device__ float g_h   [Sq*Dm];      // rmsnorm(x)
__device__ float g_q   [Sq*HD];
__device__ float g_k   [Sq*KVD];
__device__ float g_v   [Sq*KVD];
__device__ float g_o   [Sq*HD];      // attention output [S, H*DH]
__device__ float g_t   [Sq*Dm];      // rmsnorm(x1)
__device__ float g_gate[En*Sq*Id];   // gate, then act (in place)
__device__ float g_up  [En*Sq*Id];
__device__ float g_moe [2*Sq*Dm];    // per-topk-slot MoE contribution
__device__ int   g_cnt [En];
__device__ int   g_ptok[En*Sq];
__device__ float g_pw  [En*Sq];
__device__ int   g_pslot[En*Sq];

// ---------------- rmsnorm ----------------
__global__ __launch_bounds__(256) void rmsnorm_k(const float* __restrict__ in,
                                                 const float* __restrict__ w,
                                                 float* __restrict__ out, int cols) {
    int row = blockIdx.x;
    const float* r = in + (size_t)row * cols;
    float ss = 0.f;
    for (int i = threadIdx.x; i < cols; i += 256) { float v = r[i]; ss += v * v; }
    __shared__ float red[256];
    red[threadIdx.x] = ss; __syncthreads();
    for (int st = 128; st > 0; st >>= 1) {
        if (threadIdx.x < st) red[threadIdx.x] += red[threadIdx.x + st];
        __syncthreads();
    }
    float scale = rsqrtf(red[0] / (float)cols + EPSf);
    for (int i = threadIdx.x; i < cols; i += 256)
        out[(size_t)row * cols + i] = r[i] * scale * w[i];
}

// ---------------- plain GEMM: C[M,N] = A[M,K]@B[K,N] (+res) ----------------
// M,N multiples of 64; K multiple of 16. 256 threads, 4x4 micro-tile.
__global__ __launch_bounds__(256) void gemm_k(const float* __restrict__ A,
                                              const float* __restrict__ B,
                                              float* __restrict__ C,
                                              const float* __restrict__ res,
                                              int M, int N, int K) {
    __shared__ float As[16][64];
    __shared__ float Bs[16][64];
    int tid = threadIdx.x, tx = tid & 15, ty = tid >> 4;
    int m0 = blockIdx.y * 64, n0 = blockIdx.x * 64;
    float acc[4][4] = {};
    for (int k0 = 0; k0 < K; k0 += 16) {
#pragma unroll
        for (int i = 0; i < 4; i++) {
            int e = tid + i * 256; int m = e >> 4, k = e & 15;
            As[k][m] = A[(size_t)(m0 + m) * K + k0 + k];
        }
#pragma unroll
        for (int i = 0; i < 4; i++) {
            int e = tid + i * 256; int k = e >> 6, n = e & 63;
            Bs[k][n] = B[(size_t)(k0 + k) * N + n0 + n];
        }
        __syncthreads();
#pragma unroll
        for (int k = 0; k < 16; k++) {
            float4 a = *(const float4*)&As[k][ty * 4];
            float4 b = *(const float4*)&Bs[k][tx * 4];
            float av[4] = {a.x, a.y, a.z, a.w};
            float bv[4] = {b.x, b.y, b.z, b.w};
#pragma unroll
            for (int i = 0; i < 4; i++)
#pragma unroll
                for (int j = 0; j < 4; j++) acc[i][j] += av[i] * bv[j];
        }
        __syncthreads();
    }
#pragma unroll
    for (int i = 0; i < 4; i++) {
        int m = m0 + ty * 4 + i;
#pragma unroll
        for (int j = 0; j < 4; j++) {
            int n = n0 + tx * 4 + j;
            float v = acc[i][j];
            if (res) v += res[(size_t)m * N + n];
            C[(size_t)m * N + n] = v;
        }
    }
}

// ---------------- RoPE (partial, RD=64) ----------------
__global__ __launch_bounds__(256) void rope_k(float* __restrict__ q, int nheads) {
    int idx = blockIdx.x * 256 + threadIdx.x;             // S*nheads*32 total
    int d = idx & 31;
    int h = (idx >> 5) % nheads;
    int s = idx / (32 * nheads);
    float inv = powf(1.0e6f, -(float)d / 32.f);
    float ang = (float)s * inv;
    float c = cosf(ang), sn = sinf(ang);
    float* base = q + (size_t)s * (nheads * DHd) + h * DHd;
    float x1 = base[d], x2 = base[d + 32];
    base[d]      = x1 * c - x2 * sn;
    base[d + 32] = x2 * c + x1 * sn;
}

// ---------------- flash attention (fp32, causal, GQA) ----------------
// grid (32 qblocks, 16 heads), 256 threads, dynamic smem.
__global__ __launch_bounds__(256) void attn_k(const float* __restrict__ q,
                                              const float* __restrict__ k,
                                              const float* __restrict__ v,
                                              float* __restrict__ o) {
    extern __shared__ float sm[];
    float* Qs = sm;                    // 64 x 129
    float* Ks = Qs + 64 * 129;         // 64 x 129
    float* Vs = Ks + 64 * 129;         // 64 x 128
    float* Ps = Vs + 64 * 128;         // 64 x 65
    float* Mrow = Ps + 64 * 65;        // 64
    float* Lrow = Mrow + 64;           // 64
    int qb = gridDim.x - 1 - blockIdx.x;   // heavy tiles first
    int h  = blockIdx.y;
    int kvh = h >> 2;
    int tid = threadIdx.x, tx = tid & 15, ty = tid >> 4;
    const float scale = 0.08838834764831845f;  // 1/sqrt(128)

    for (int i = tid; i < 64 * 128; i += 256) {
        int r = i >> 7, c = i & 127;
        Qs[r * 129 + c] = q[(size_t)(qb * 64 + r) * HD + h * DHd + c];
    }
    if (tid < 64) { Mrow[tid] = -INFINITY; Lrow[tid] = 0.f; }
    float accO[4][8] = {};

    for (int kb = 0; kb <= qb; kb++) {
        for (int i = tid; i < 64 * 128; i += 256) {
            int r = i >> 7, c = i & 127;
            size_t src = (size_t)(kb * 64 + r) * KVD + kvh * DHd + c;
            Ks[r * 129 + c] = k[src];
            Vs[r * 128 + c] = v[src];
        }
        __syncthreads();

        // S = Q @ K^T  (4x4 per thread)
        float sc[4][4] = {};
#pragma unroll 4
        for (int kk = 0; kk < 128; kk++) {
            float a[4], b[4];
#pragma unroll
            for (int i = 0; i < 4; i++) a[i] = Qs[(ty * 4 + i) * 129 + kk];
#pragma unroll
            for (int j = 0; j < 4; j++) b[j] = Ks[(tx * 4 + j) * 129 + kk];
#pragma unroll
            for (int i = 0; i < 4; i++)
#pragma unroll
                for (int j = 0; j < 4; j++) sc[i][j] += a[i] * b[j];
        }
        // scale + causal mask
#pragma unroll
        for (int i = 0; i < 4; i++) {
            int qrow = qb * 64 + ty * 4 + i;
#pragma unroll
            for (int j = 0; j < 4; j++) {
                int kcol = kb * 64 + tx * 4 + j;
                sc[i][j] = (kcol <= qrow) ? sc[i][j] * scale : -INFINITY;
            }
        }
        // online softmax per row (row group = 16 lanes sharing ty)
#pragma unroll
        for (int i = 0; i < 4; i++) {
            int row = ty * 4 + i;
            float mloc = -INFINITY;
#pragma unroll
            for (int j = 0; j < 4; j++) mloc = fmaxf(mloc, sc[i][j]);
            for (int off = 8; off > 0; off >>= 1)
                mloc = fmaxf(mloc, __shfl_xor_sync(0xffffffffu, mloc, off));
            float mold = Mrow[row];
            float mnew = fmaxf(mold, mloc);
            float alpha = expf(mold - mnew);
            float ls = 0.f;
#pragma unroll
            for (int j = 0; j < 4; j++) {
                float p = expf(sc[i][j] - mnew);
                Ps[row * 65 + tx * 4 + j] = p;
                ls += p;
            }
            for (int off = 8; off > 0; off >>= 1)
                ls += __shfl_xor_sync(0xffffffffu, ls, off);
#pragma unroll
            for (int c = 0; c < 8; c++) accO[i][c] *= alpha;
            if (tx == 0) { Mrow[row] = mnew; Lrow[row] = Lrow[row] * alpha + ls; }
        }
        __syncthreads();

        // O += P @ V  (4 rows x 8 cols per thread)
#pragma unroll 4
        for (int kk = 0; kk < 64; kk++) {
            float a[4];
#pragma unroll
            for (int i = 0; i < 4; i++) a[i] = Ps[(ty * 4 + i) * 65 + kk];
            float4 v0 = *(const float4*)&Vs[kk * 128 + tx * 8];
            float4 v1 = *(const float4*)&Vs[kk * 128 + tx * 8 + 4];
#pragma unroll
            for (int i = 0; i < 4; i++) {
                accO[i][0] += a[i] * v0.x; accO[i][1] += a[i] * v0.y;
                accO[i][2] += a[i] * v0.z; accO[i][3] += a[i] * v0.w;
                accO[i][4] += a[i] * v1.x; accO[i][5] += a[i] * v1.y;
                accO[i][6] += a[i] * v1.z; accO[i][7] += a[i] * v1.w;
            }
        }
        __syncthreads();
    }
#pragma unroll
    for (int i = 0; i < 4; i++) {
        int row = ty * 4 + i;
        float inv = 1.f / Lrow[row];
#pragma unroll
        for (int j = 0; j < 8; j++)
            o[(size_t)(qb * 64 + row) * HD + h * DHd + tx * 8 + j] = accO[i][j] * inv;
    }
}

// ---------------- router ----------------
__global__ __launch_bounds__(256) void reset_k() {
    if (threadIdx.x < En) g_cnt[threadIdx.x] = 0;
}

__global__ __launch_bounds__(256) void router_k(const float* __restrict__ Tm,
                                                const float* __restrict__ rw,
                                                const float* __restrict__ rb) {
    int row = blockIdx.x, tid = threadIdx.x;
    const float* r = Tm + (size_t)row * Dm;
    float loc[En] = {};
    for (int d = tid; d < Dm; d += 256) {
        float x = r[d];
#pragma unroll
        for (int e = 0; e < En; e++) loc[e] += x * rw[d * En + e];
    }
    __shared__ float sred[256 * En];
#pragma unroll
    for (int e = 0; e < En; e++) sred[tid * En + e] = loc[e];
    __syncthreads();
    for (int st = 128; st > 0; st >>= 1) {
        if (tid < st)
#pragma unroll
            for (int e = 0; e < En; e++) sred[tid * En + e] += sred[(tid + st) * En + e];
        __syncthreads();
    }
    if (tid == 0) {
        float sig[En], scv[En];
#pragma unroll
        for (int e = 0; e < En; e++) {
            float l = sred[e];
            sig[e] = 1.f / (1.f + expf(-l));
            scv[e] = sig[e] + rb[e];
        }
        int i0 = 0;
#pragma unroll
        for (int e = 1; e < En; e++) if (scv[e] > scv[i0]) i0 = e;
        int i1 = -1;
#pragma unroll
        for (int e = 0; e < En; e++)
            if (e != i0 && (i1 < 0 || scv[e] > scv[i1])) i1 = e;
        float a0 = sig[i0], a1 = sig[i1], s = a0 + a1;
        float w0 = a0 / s, w1 = a1 / s;
        int p = atomicAdd(&g_cnt[i0], 1);
        g_ptok[i0 * Sq + p] = row; g_pw[i0 * Sq + p] = w0; g_pslot[i0 * Sq + p] = 0;
        p = atomicAdd(&g_cnt[i1], 1);
        g_ptok[i1 * Sq + p] = row; g_pw[i1 * Sq + p] = w1; g_pslot[i1 * Sq + p] = 1;
    }
}

// ---------------- grouped GEMM (gather rows of t): C_e = T[perm_e] @ B_e ----------------
__global__ __launch_bounds__(256) void gemm_gather_k(const float* __restrict__ Tm,
                                                     const float* __restrict__ Ball,
                                                     float* __restrict__ Call,
                                                     int N, int K) {
    int e = blockIdx.z;
    int cnt = g_cnt[e];
    int m0 = blockIdx.y * 64;
    if (m0 >= cnt) return;
    int n0 = blockIdx.x * 64;
    const float* B = Ball + (size_t)e * K * N;
    float* C = Call + (size_t)e * Sq * N;
    __shared__ float As[16][64];
    __shared__ float Bs[16][64];
    __shared__ int toks[64];
    int tid = threadIdx.x, tx = tid & 15, ty = tid >> 4;
    if (tid < 64) toks[tid] = (m0 + tid < cnt) ? g_ptok[e * Sq + m0 + tid] : -1;
    __syncthreads();
    float acc[4][4] = {};
    for (int k0 = 0; k0 < K; k0 += 16) {
#pragma unroll
        for (int i = 0; i < 4; i++) {
            int e2 = tid + i * 256; int m = e2 >> 4, k = e2 & 15;
            int t = toks[m];
            As[k][m] = (t >= 0) ? Tm[(size_t)t * K + k0 + k] : 0.f;
        }
#pragma unroll
        for (int i = 0; i < 4; i++) {
            int e2 = tid + i * 256; int k = e2 >> 6, n = e2 & 63;
            Bs[k][n] = B[(size_t)(k0 + k) * N + n0 + n];
        }
        __syncthreads();
#pragma unroll
        for (int k = 0; k < 16; k++) {
            float4 a = *(const float4*)&As[k][ty * 4];
            float4 b = *(const float4*)&Bs[k][tx * 4];
            float av[4] = {a.x, a.y, a.z, a.w};
            float bv[4] = {b.x, b.y, b.z, b.w};
#pragma unroll
            for (int i = 0; i < 4; i++)
#pragma unroll
                for (int j = 0; j < 4; j++) acc[i][j] += av[i] * bv[j];
        }
        __syncthreads();
    }
#pragma unroll
    for (int i = 0; i < 4; i++) {
        int m = m0 + ty * 4 + i;
        if (m < cnt)
#pragma unroll
            for (int j = 0; j < 4; j++)
                C[(size_t)m * N + n0 + tx * 4 + j] = acc[i][j];
    }
}

// ---------------- act = silu(gate)*up (in place into g_gate) ----------------
__global__ __launch_bounds__(256) void act_k() {
    int e = blockIdx.z;
    int cnt = g_cnt[e];
    int i = blockIdx.x * 256 + threadIdx.x;   // over Sq*Id
    int row = i >> 10;
    if (row >= cnt) return;
    size_t idx = (size_t)e * Sq * Id + i;
    float g = g_gate[idx];
    float u = g_up[idx];
    g_gate[idx] = (g / (1.f + expf(-g))) * u;
}

// ---------------- grouped GEMM down + weighted scatter ----------------
__global__ __launch_bounds__(256) void gemm_scatter_k(const float* __restrict__ Aall,
                                                      const float* __restrict__ Ball,
                                                      int N, int K) {
    int e = blockIdx.z;
    int cnt = g_cnt[e];
    int m0 = blockIdx.y * 64;
    if (m0 >= cnt) return;
    int n0 = blockIdx.x * 64;
    const float* A = Aall + (size_t)e * Sq * K;
    const float* B = Ball + (size_t)e * K * N;
    __shared__ float As[16][64];
    __shared__ float Bs[16][64];
    __shared__ int stok[64]; __shared__ float swt[64]; __shared__ int ssl[64];
    int tid = threadIdx.x, tx = tid & 15, ty = tid >> 4;
    if (tid < 64) {
        int ok = (m0 + tid < cnt);
        stok[tid] = ok ? g_ptok[e * Sq + m0 + tid] : 0;
        swt[tid]  = ok ? g_pw[e * Sq + m0 + tid]  : 0.f;
        ssl[tid]  = ok ? g_pslot[e * Sq + m0 + tid] : 0;
    }
    __syncthreads();
    float acc[4][4] = {};
    for (int k0 = 0; k0 < K; k0 += 16) {
#pragma unroll
        for (int i = 0; i < 4; i++) {
            int e2 = tid + i * 256; int m = e2 >> 4, k = e2 & 15;
            As[k][m] = (m0 + m < cnt) ? A[(size_t)(m0 + m) * K + k0 + k] : 0.f;
        }
#pragma unroll
        for (int i = 0; i < 4; i++) {
            int e2 = tid + i * 256; int k = e2 >> 6, n = e2 & 63;
            Bs[k][n] = B[(size_t)(k0 + k) * N + n0 + n];
        }
        __syncthreads();
#pragma unroll
        for (int k = 0; k < 16; k++) {
            float4 a = *(const float4*)&As[k][ty * 4];
            float4 b = *(const float4*)&Bs[k][tx * 4];
            float av[4] = {a.x, a.y, a.z, a.w};
            float bv[4] = {b.x, b.y, b.z, b.w};
#pragma unroll
            for (int i = 0; i < 4; i++)
#pragma unroll
                for (int j = 0; j < 4; j++) acc[i][j] += av[i] * bv[j];
        }
        __syncthreads();
    }
#pragma unroll
    for (int i = 0; i < 4; i++) {
        int m = ty * 4 + i;
        if (m0 + m < cnt) {
            int token = stok[m]; float w = swt[m]; int slot = ssl[m];
            float* dst = g_moe + ((size_t)slot * Sq + token) * Dm + n0 + tx * 4;
#pragma unroll
            for (int j = 0; j < 4; j++) dst[j] = w * acc[i][j];
        }
    }
}

// ---------------- final: out = x1 + moe0 + moe1 ----------------
__global__ __launch_bounds__(256) void final_add_k(float* __restrict__ out) {
    int i = blockIdx.x * 256 + threadIdx.x;
    out[i] = out[i] + g_moe[i] + g_moe[(size_t)Sq * Dm + i];
}

// ---------------- host orchestration ----------------
extern "C" void kernel_launch(void* const* d_in, const int* in_sizes, int n_in,
                              void* d_out, int out_size) {
    const float* x    = (const float*)d_in[0];
    const float* ln1  = (const float*)d_in[1];
    const float* ln2  = (const float*)d_in[2];
    const float* wq   = (const float*)d_in[3];
    const float* wk   = (const float*)d_in[4];
    const float* wv   = (const float*)d_in[5];
    const float* wo   = (const float*)d_in[6];
    const float* qn   = (const float*)d_in[7];
    const float* kn   = (const float*)d_in[8];
    const float* rw   = (const float*)d_in[9];
    const float* rb   = (const float*)d_in[10];
    const float* wg   = (const float*)d_in[11];
    const float* wu   = (const float*)d_in[12];
    const float* wd   = (const float*)d_in[13];
    float* out = (float*)d_out;

    float *ph, *pq, *pk, *pv, *po, *pt, *pgate, *pup;
    cudaGetSymbolAddress((void**)&ph,    g_h);
    cudaGetSymbolAddress((void**)&pq,    g_q);
    cudaGetSymbolAddress((void**)&pk,    g_k);
    cudaGetSymbolAddress((void**)&pv,    g_v);
    cudaGetSymbolAddress((void**)&po,    g_o);
    cudaGetSymbolAddress((void**)&pt,    g_t);
    cudaGetSymbolAddress((void**)&pgate, g_gate);
    cudaGetSymbolAddress((void**)&pup,   g_up);

    int attn_smem = (64 * 129 * 2 + 64 * 128 + 64 * 65 + 128) * 4;  // 115968 B
    cudaFuncSetAttribute(attn_k, cudaFuncAttributeMaxDynamicSharedMemorySize, attn_smem);

    // 1. h = rmsnorm(x, ln1)
    rmsnorm_k<<<Sq, 256>>>(x, ln1, ph, Dm);
    // 2. q,k,v projections
    gemm_k<<<dim3(HD / 64, Sq / 64), 256>>>(ph, wq, pq, nullptr, Sq, HD, Dm);
    gemm_k<<<dim3(KVD / 64, Sq / 64), 256>>>(ph, wk, pk, nullptr, Sq, KVD, Dm);
    gemm_k<<<dim3(KVD / 64, Sq / 64), 256>>>(ph, wv, pv, nullptr, Sq, KVD, Dm);
    // 3. q/k rmsnorm (full-width)
    rmsnorm_k<<<Sq, 256>>>(pq, qn, pq, HD);
    rmsnorm_k<<<Sq, 256>>>(pk, kn, pk, KVD);
    // 4. RoPE
    rope_k<<<(Sq * Hn * 32) / 256, 256>>>(pq, Hn);
    rope_k<<<(Sq * KVn * 32) / 256, 256>>>(pk, KVn);
    // 5. attention
    attn_k<<<dim3(Sq / 64, Hn), 256, attn_smem>>>(pq, pk, pv, po);
    // 6. x1 = x + o @ wo  -> d_out
    gemm_k<<<dim3(Dm / 64, Sq / 64), 256>>>(po, wo, out, x, Sq, Dm, HD);
    // 7. t = rmsnorm(x1, ln2)
    rmsnorm_k<<<Sq, 256>>>(out, ln2, pt, Dm);
    // 8. routing
    reset_k<<<1, 256>>>();
    router_k<<<Sq, 256>>>(pt, rw, rb);
    // 9. expert gate/up GEMMs (gathered)
    gemm_gather_k<<<dim3(Id / 64, Sq / 64, En), 256>>>(pt, wg, pgate, Id, Dm);
    gemm_gather_k<<<dim3(Id / 64, Sq / 64, En), 256>>>(pt, wu, pup, Id, Dm);
    // 10. act = silu(gate)*up
    act_k<<<dim3((Sq * Id) / 256, 1, En), 256>>>();
    // 11. down GEMM + weighted scatter into slot buffers
    gemm_scatter_k<<<dim3(Dm / 64, Sq / 64, En), 256>>>(pgate, wd, Dm, Id);
    // 12. out = x1 + moe
    final_add_k<<<(Sq * Dm) / 256, 256>>>(out);
}

// round 2
// speedup vs baseline: 1.0181x; 1.0181x over previous
#include <cuda_runtime.h>
#include <math.h>

// ---------------- problem constants ----------------
#define Sq   2048   // sequence length (B=1)
#define Dm   2048   // model dim
#define Hn   16     // query heads
#define KVn  4      // kv heads
#define DHd  128    // head dim
#define En   8      // experts
#define Id   1024   // expert intermediate
#define HD   2048   // Hn*DHd
#define KVD  512    // KVn*DHd
#define EPSf 1e-6f

// ---------------- static device scratch ----------------
__device__ float g_h   [Sq*Dm];      // rmsnorm(x)
__device__ float g_q   [Sq*HD];
__device__ float g_k   [Sq*KVD];
__device__ float g_v   [Sq*KVD];
__device__ float g_o   [Sq*HD];      // attention output [S, H*DH]
__device__ float g_t   [Sq*Dm];      // rmsnorm(x1)
__device__ float g_gate[En*Sq*Id];   // gate, then act (in place)
__device__ float g_up  [En*Sq*Id];
__device__ float g_moe [2*Sq*Dm];    // per-topk-slot MoE contribution
__device__ int   g_cnt [En];
__device__ int   g_ptok[En*Sq];
__device__ float g_pw  [En*Sq];
__device__ int   g_pslot[En*Sq];

// ---------------- rmsnorm ----------------
__global__ __launch_bounds__(256) void rmsnorm_k(const float* __restrict__ in,
                                                 const float* __restrict__ w,
                                                 float* __restrict__ out, int cols) {
    int row = blockIdx.x;
    const float* r = in + (size_t)row * cols;
    float ss = 0.f;
    for (int i = threadIdx.x; i < cols; i += 256) { float v = r[i]; ss += v * v; }
    __shared__ float red[256];
    red[threadIdx.x] = ss; __syncthreads();
    for (int st = 128; st > 0; st >>= 1) {
        if (threadIdx.x < st) red[threadIdx.x] += red[threadIdx.x + st];
        __syncthreads();
    }
    float scale = rsqrtf(red[0] / (float)cols + EPSf);
    for (int i = threadIdx.x; i < cols; i += 256)
        out[(size_t)row * cols + i] = r[i] * scale * w[i];
}

// ---------------- plain GEMM: C[M,N] = A[M,K]@B[K,N] (+res) ----------------
// M,N multiples of 64; K multiple of 16. 256 threads, 4x4 micro-tile.
__global__ __launch_bounds__(256) void gemm_k(const float* __restrict__ A,
                                              const float* __restrict__ B,
                                              float* __restrict__ C,
                                              const float* __restrict__ res,
                                              int M, int N, int K) {
    __shared__ float As[16][64];
    __shared__ float Bs[16][64];
    int tid = threadIdx.x, tx = tid & 15, ty = tid >> 4;
    int m0 = blockIdx.y * 64, n0 = blockIdx.x * 64;
    float acc[4][4] = {};
    for (int k0 = 0; k0 < K; k0 += 16) {
#pragma unroll
        for (int i = 0; i < 4; i++) {
            int e = tid + i * 256; int m = e >> 4, k = e & 15;
            As[k][m] = A[(size_t)(m0 + m) * K + k0 + k];
        }
#pragma unroll
        for (int i = 0; i < 4; i++) {
            int e = tid + i * 256; int k = e >> 6, n = e & 63;
            Bs[k][n] = B[(size_t)(k0 + k) * N + n0 + n];
        }
        __syncthreads();
#pragma unroll
        for (int k = 0; k < 16; k++) {
            float4 a = *(const float4*)&As[k][ty * 4];
            float4 b = *(const float4*)&Bs[k][tx * 4];
            float av[4] = {a.x, a.y, a.z, a.w};
            float bv[4] = {b.x, b.y, b.z, b.w};
#pragma unroll
            for (int i = 0; i < 4; i++)
#pragma unroll
                for (int j = 0; j < 4; j++) acc[i][j] += av[i] * bv[j];
        }
        __syncthreads();
    }
#pragma unroll
    for (int i = 0; i < 4; i++) {
        int m = m0 + ty * 4 + i;
#pragma unroll
        for (int j = 0; j < 4; j++) {
            int n = n0 + tx * 4 + j;
            float v = acc[i][j];
            if (res) v += res[(size_t)m * N + n];
            C[(size_t)m * N + n] = v;
        }
    }
}

// ---------------- RoPE (partial, RD=64) ----------------
__global__ __launch_bounds__(256) void rope_k(float* __restrict__ q, int nheads) {
    int idx = blockIdx.x * 256 + threadIdx.x;             // S*nheads*32 total
    int d = idx & 31;
    int h = (idx >> 5) % nheads;
    int s = idx / (32 * nheads);
    float inv = powf(1.0e6f, -(float)d / 32.f);
    float ang = (float)s * inv;
    float c = cosf(ang), sn = sinf(ang);
    float* base = q + (size_t)s * (nheads * DHd) + h * DHd;
    float x1 = base[d], x2 = base[d + 32];
    base[d]      = x1 * c - x2 * sn;
    base[d + 32] = x2 * c + x1 * sn;
}

// ---------------- flash attention (fp32, causal, GQA) ----------------
// grid (32 qblocks, 16 heads), 256 threads, dynamic smem.
__global__ __launch_bounds__(256) void attn_k(const float* __restrict__ q,
                                              const float* __restrict__ k,
                                              const float* __restrict__ v,
                                              float* __restrict__ o) {
    extern __shared__ float sm[];
    float* Qs = sm;                    // 64 x 129
    float* Ks = Qs + 64 * 129;         // 64 x 129
    float* Vs = Ks + 64 * 129;         // 64 x 128
    float* Ps = Vs + 64 * 128;         // 64 x 65
    float* Mrow = Ps + 64 * 65;        // 64
    float* Lrow = Mrow + 64;           // 64
    int qb = gridDim.x - 1 - blockIdx.x;   // heavy tiles first
    int h  = blockIdx.y;
    int kvh = h >> 2;
    int tid = threadIdx.x, tx = tid & 15, ty = tid >> 4;
    const float scale = 0.08838834764831845f;  // 1/sqrt(128)

    for (int i = tid; i < 64 * 128; i += 256) {
        int r = i >> 7, c = i & 127;
        Qs[r * 129 + c] = q[(size_t)(qb * 64 + r) * HD + h * DHd + c];
    }
    if (tid < 64) { Mrow[tid] = -INFINITY; Lrow[tid] = 0.f; }
    float accO[4][8] = {};

    for (int kb = 0; kb <= qb; kb++) {
        for (int i = tid; i < 64 * 128; i += 256) {
            int r = i >> 7, c = i & 127;
            size_t src = (size_t)(kb * 64 + r) * KVD + kvh * DHd + c;
            Ks[r * 129 + c] = k[src];
            Vs[r * 128 + c] = v[src];
        }
        __syncthreads();

        // S = Q @ K^T  (4x4 per thread)
        float sc[4][4] = {};
#pragma unroll 4
        for (int kk = 0; kk < 128; kk++) {
            float a[4], b[4];
#pragma unroll
            for (int i = 0; i < 4; i++) a[i] = Qs[(ty * 4 + i) * 129 + kk];
#pragma unroll
            for (int j = 0; j < 4; j++) b[j] = Ks[(tx * 4 + j) * 129 + kk];
#pragma unroll
            for (int i = 0; i < 4; i++)
#pragma unroll
                for (int j = 0; j < 4; j++) sc[i][j] += a[i] * b[j];
        }
        // scale + causal mask
#pragma unroll
        for (int i = 0; i < 4; i++) {
            int qrow = qb * 64 + ty * 4 + i;
#pragma unroll
            for (int j = 0; j < 4; j++) {
                int kcol = kb * 64 + tx * 4 + j;
                sc[i][j] = (kcol <= qrow) ? sc[i][j] * scale : -INFINITY;
            }
        }
        // online softmax per row (row group = 16 lanes sharing ty)
#pragma unroll
        for (int i = 0; i < 4; i++) {
            int row = ty * 4 + i;
            float mloc = -INFINITY;
#pragma unroll
            for (int j = 0; j < 4; j++) mloc = fmaxf(mloc, sc[i][j]);
            for (int off = 8; off > 0; off >>= 1)
                mloc = fmaxf(mloc, __shfl_xor_sync(0xffffffffu, mloc, off));
            float mold = Mrow[row];
            float mnew = fmaxf(mold, mloc);
            float alpha = expf(mold - mnew);
            float ls = 0.f;
#pragma unroll
            for (int j = 0; j < 4; j++) {
                float p = expf(sc[i][j] - mnew);
                Ps[row * 65 + tx * 4 + j] = p;
                ls += p;
            }
            for (int off = 8; off > 0; off >>= 1)
                ls += __shfl_xor_sync(0xffffffffu, ls, off);
#pragma unroll
            for (int c = 0; c < 8; c++) accO[i][c] *= alpha;
            if (tx == 0) { Mrow[row] = mnew; Lrow[row] = Lrow[row] * alpha + ls; }
        }
        __syncthreads();

        // O += P @ V  (4 rows x 8 cols per thread)
#pragma unroll 4
        for (int kk = 0; kk < 64; kk++) {
            float a[4];
#pragma unroll
            for (int i = 0; i < 4; i++) a[i] = Ps[(ty * 4 + i) * 65 + kk];
            float4 v0 = *(const float4*)&Vs[kk * 128 + tx * 8];
            float4 v1 = *(const float4*)&Vs[kk * 128 + tx * 8 + 4];
#pragma unroll
            for (int i = 0; i < 4; i++) {
                accO[i][0] += a[i] * v0.x; accO[i][1] += a[i] * v0.y;
                accO[i][2] += a[i] * v0.z; accO[i][3] += a[i] * v0.w;
                accO[i][4] += a[i] * v1.x; accO[i][5] += a[i] * v1.y;
                accO[i][6] += a[i] * v1.z; accO[i][7] += a[i] * v1.w;
            }
        }
        __syncthreads();
    }
#pragma unroll
    for (int i = 0; i < 4; i++) {
        int row = ty * 4 + i;
        float inv = 1.f / Lrow[row];
#pragma unroll
        for (int j = 0; j < 8; j++)
            o[(size_t)(qb * 64 + row) * HD + h * DHd + tx * 8 + j] = accO[i][j] * inv;
    }
}

// ---------------- router ----------------
__global__ __launch_bounds__(256) void reset_k() {
    if (threadIdx.x < En) g_cnt[threadIdx.x] = 0;
}

__global__ __launch_bounds__(256) void router_k(const float* __restrict__ Tm,
                                                const float* __restrict__ rw,
                                                const float* __restrict__ rb) {
    int row = blockIdx.x, tid = threadIdx.x;
    const float* r = Tm + (size_t)row * Dm;
    float loc[En] = {};
    for (int d = tid; d < Dm; d += 256) {
        float x = r[d];
#pragma unroll
        for (int e = 0; e < En; e++) loc[e] += x * rw[d * En + e];
    }
    __shared__ float sred[256 * En];
#pragma unroll
    for (int e = 0; e < En; e++) sred[tid * En + e] = loc[e];
    __syncthreads();
    for (int st = 128; st > 0; st >>= 1) {
        if (tid < st)
#pragma unroll
            for (int e = 0; e < En; e++) sred[tid * En + e] += sred[(tid + st) * En + e];
        __syncthreads();
    }
    if (tid == 0) {
        float sig[En], scv[En];
#pragma unroll
        for (int e = 0; e < En; e++) {
            float l = sred[e];
            sig[e] = 1.f / (1.f + expf(-l));
            scv[e] = sig[e] + rb[e];
        }
        int i0 = 0;
#pragma unroll
        for (int e = 1; e < En; e++) if (scv[e] > scv[i0]) i0 = e;
        int i1 = -1;
#pragma unroll
        for (int e = 0; e < En; e++)
            if (e != i0 && (i1 < 0 || scv[e] > scv[i1])) i1 = e;
        float a0 = sig[i0], a1 = sig[i1], s = a0 + a1;
        float w0 = a0 / s, w1 = a1 / s;
        int p = atomicAdd(&g_cnt[i0], 1);
        g_ptok[i0 * Sq + p] = row; g_pw[i0 * Sq + p] = w0; g_pslot[i0 * Sq + p] = 0;
        p = atomicAdd(&g_cnt[i1], 1);
        g_ptok[i1 * Sq + p] = row; g_pw[i1 * Sq + p] = w1; g_pslot[i1 * Sq + p] = 1;
    }
}

// ---------------- grouped GEMM (gather rows of t): C_e = T[perm_e] @ B_e ----------------
__global__ __launch_bounds__(256) void gemm_gather_k(const float* __restrict__ Tm,
                                                     const float* __restrict__ Ball,
                                                     float* __restrict__ Call,
                                                     int N, int K) {
    int e = blockIdx.z;
    int cnt = g_cnt[e];
    int m0 = blockIdx.y * 64;
    if (m0 >= cnt) return;
    int n0 = blockIdx.x * 64;
    const float* B = Ball + (size_t)e * K * N;
    float* C = Call + (size_t)e * Sq * N;
    __shared__ float As[16][64];
    __shared__ float Bs[16][64];
    __shared__ int toks[64];
    int tid = threadIdx.x, tx = tid & 15, ty = tid >> 4;
    if (tid < 64) toks[tid] = (m0 + tid < cnt) ? g_ptok[e * Sq + m0 + tid] : -1;
    __syncthreads();
    float acc[4][4] = {};
    for (int k0 = 0; k0 < K; k0 += 16) {
#pragma unroll
        for (int i = 0; i < 4; i++) {
            int e2 = tid + i * 256; int m = e2 >> 4, k = e2 & 15;
            int t = toks[m];
            As[k][m] = (t >= 0) ? Tm[(size_t)t * K + k0 + k] : 0.f;
        }
#pragma unroll
        for (int i = 0; i < 4; i++) {
            int e2 = tid + i * 256; int k = e2 >> 6, n = e2 & 63;
            Bs[k][n] = B[(size_t)(k0 + k) * N + n0 + n];
        }
        __syncthreads();
#pragma unroll
        for (int k = 0; k < 16; k++) {
            float4 a = *(const float4*)&As[k][ty * 4];
            float4 b = *(const float4*)&Bs[k][tx * 4];
            float av[4] = {a.x, a.y, a.z, a.w};
            float bv[4] = {b.x, b.y, b.z, b.w};
#pragma unroll
            for (int i = 0; i < 4; i++)
#pragma unroll
                for (int j = 0; j < 4; j++) acc[i][j] += av[i] * bv[j];
        }
        __syncthreads();
    }
#pragma unroll
    for (int i = 0; i < 4; i++) {
        int m = m0 + ty * 4 + i;
        if (m < cnt)
#pragma unroll
            for (int j = 0; j < 4; j++)
                C[(size_t)m * N + n0 + tx * 4 + j] = acc[i][j];
    }
}

// ---------------- act = silu(gate)*up (in place into g_gate) ----------------
__global__ __launch_bounds__(256) void act_k() {
    int e = blockIdx.z;
    int cnt = g_cnt[e];
    int i = blockIdx.x * 256 + threadIdx.x;   // over Sq*Id
    int row = i >> 10;
    if (row >= cnt) return;
    size_t idx = (size_t)e * Sq * Id + i;
    float g = g_gate[idx];
    float u = g_up[idx];
    g_gate[idx] = (g / (1.f + expf(-g))) * u;
}

// ---------------- grouped GEMM down + weighted scatter ----------------
__global__ __launch_bounds__(256) void gemm_scatter_k(const float* __restrict__ Aall,
                                                      const float* __restrict__ Ball,
                                                      int N, int K) {
    int e = blockIdx.z;
    int cnt = g_cnt[e];
    int m0 = blockIdx.y * 64;
    if (m0 >= cnt) return;
    int n0 = blockIdx.x * 64;
    const float* A = Aall + (size_t)e * Sq * K;
    const float* B = Ball + (size_t)e * K * N;
    __shared__ float As[16][64];
    __shared__ float Bs[16][64];
    __shared__ int stok[64]; __shared__ float swt[64]; __shared__ int ssl[64];
    int tid = threadIdx.x, tx = tid & 15, ty = tid >> 4;
    if (tid < 64) {
        int ok = (m0 + tid < cnt);
        stok[tid] = ok ? g_ptok[e * Sq + m0 + tid] : 0;
        swt[tid]  = ok ? g_pw[e * Sq + m0 + tid]  : 0.f;
        ssl[tid]  = ok ? g_pslot[e * Sq + m0 + tid] : 0;
    }
    __syncthreads();
    float acc[4][4] = {};
    for (int k0 = 0; k0 < K; k0 += 16) {
#pragma unroll
        for (int i = 0; i < 4; i++) {
            int e2 = tid + i * 256; int m = e2 >> 4, k = e2 & 15;
            As[k][m] = (m0 + m < cnt) ? A[(size_t)(m0 + m) * K + k0 + k] : 0.f;
        }
#pragma unroll
        for (int i = 0; i < 4; i++) {
            int e2 = tid + i * 256; int k = e2 >> 6, n = e2 & 63;
            Bs[k][n] = B[(size_t)(k0 + k) * N + n0 + n];
        }
        __syncthreads();
#pragma unroll
        for (int k = 0; k < 16; k++) {
            float4 a = *(const float4*)&As[k][ty * 4];
            float4 b = *(const float4*)&Bs[k][tx * 4];
            float av[4] = {a.x, a.y, a.z, a.w};
            float bv[4] = {b.x, b.y, b.z, b.w};
#pragma unroll
            for (int i = 0; i < 4; i++)
#pragma unroll
                for (int j = 0; j < 4; j++) acc[i][j] += av[i] * bv[j];
        }
        __syncthreads();
    }
#pragma unroll
    for (int i = 0; i < 4; i++) {
        int m = ty * 4 + i;
        if (m0 + m < cnt) {
            int token = stok[m]; float w = swt[m]; int slot = ssl[m];
            float* dst = g_moe + ((size_t)slot * Sq + token) * Dm + n0 + tx * 4;
#pragma unroll
            for (int j = 0; j < 4; j++) dst[j] = w * acc[i][j];
        }
    }
}

// ---------------- final: out = x1 + moe0 + moe1 ----------------
__global__ __launch_bounds__(256) void final_add_k(float* __restrict__ out) {
    int i = blockIdx.x * 256 + threadIdx.x;
    out[i] = out[i] + g_moe[i] + g_moe[(size_t)Sq * Dm + i];
}

// ---------------- host orchestration ----------------
extern "C" void kernel_launch(void* const* d_in, const int* in_sizes, int n_in,
                              void* d_out, int out_size) {
    const float* x    = (const float*)d_in[0];
    const float* ln1  = (const float*)d_in[1];
    const float* ln2  = (const float*)d_in[2];
    const float* wq   = (const float*)d_in[3];
    const float* wk   = (const float*)d_in[4];
    const float* wv   = (const float*)d_in[5];
    const float* wo   = (const float*)d_in[6];
    const float* qn   = (const float*)d_in[7];
    const float* kn   = (const float*)d_in[8];
    const float* rw   = (const float*)d_in[9];
    const float* rb   = (const float*)d_in[10];
    const float* wg   = (const float*)d_in[11];
    const float* wu   = (const float*)d_in[12];
    const float* wd   = (const float*)d_in[13];
    float* out = (float*)d_out;

    float *ph, *pq, *pk, *pv, *po, *pt, *pgate, *pup;
    cudaGetSymbolAddress((void**)&ph,    g_h);
    cudaGetSymbolAddress((void**)&pq,    g_q);
    cudaGetSymbolAddress((void**)&pk,    g_k);
    cudaGetSymbolAddress((void**)&pv,    g_v);
    cudaGetSymbolAddress((void**)&po,    g_o);
    cudaGetSymbolAddress((void**)&pt,    g_t);
    cudaGetSymbolAddress((void**)&pgate, g_gate);
    cudaGetSymbolAddress((void**)&pup,   g_up);

    int attn_smem = (64 * 129 * 2 + 64 * 128 + 64 * 65 + 128) * 4;  // 115968 B
    cudaFuncSetAttribute(attn_k, cudaFuncAttributeMaxDynamicSharedMemorySize, attn_smem);

    // 1. h = rmsnorm(x, ln1)
    rmsnorm_k<<<Sq, 256>>>(x, ln1, ph, Dm);
    // 2. q,k,v projections
    gemm_k<<<dim3(HD / 64, Sq / 64), 256>>>(ph, wq, pq, nullptr, Sq, HD, Dm);
    gemm_k<<<dim3(KVD / 64, Sq / 64), 256>>>(ph, wk, pk, nullptr, Sq, KVD, Dm);
    gemm_k<<<dim3(KVD / 64, Sq / 64), 256>>>(ph, wv, pv, nullptr, Sq, KVD, Dm);
    // 3. q/k rmsnorm (full-width)
    rmsnorm_k<<<Sq, 256>>>(pq, qn, pq, HD);
    rmsnorm_k<<<Sq, 256>>>(pk, kn, pk, KVD);
    // 4. RoPE
    rope_k<<<(Sq * Hn * 32) / 256, 256>>>(pq, Hn);
    rope_k<<<(Sq * KVn * 32) / 256, 256>>>(pk, KVn);
    // 5. attention
    attn_k<<<dim3(Sq / 64, Hn), 256, attn_smem>>>(pq, pk, pv, po);
    // 6. x1 = x + o @ wo  -> d_out
    gemm_k<<<dim3(Dm / 64, Sq / 64), 256>>>(po, wo, out, x, Sq, Dm, HD);
    // 7. t = rmsnorm(x1, ln2)
    rmsnorm_k<<<Sq, 256>>>(out, ln2, pt, Dm);
    // 8. routing
    reset_k<<<1, 256>>>();
    router_k<<<Sq, 256>>>(pt, rw, rb);
    // 9. expert gate/up GEMMs (gathered)
    gemm_gather_k<<<dim3(Id / 64, Sq / 64, En), 256>>>(pt, wg, pgate, Id, Dm);
    gemm_gather_k<<<dim3(Id / 64, Sq / 64, En), 256>>>(pt, wu, pup, Id, Dm);
    // 10. act = silu(gate)*up
    act_k<<<dim3((Sq * Id) / 256, 1, En), 256>>>();
    // 11. down GEMM + weighted scatter into slot buffers
    gemm_scatter_k<<<dim3(Dm / 64, Sq / 64, En), 256>>>(pgate, wd, Dm, Id);
    // 12. out = x1 + moe
    final_add_k<<<(Sq * Dm) / 256, 256>>>(out);
}

// round 4
// speedup vs baseline: 2.6381x; 2.5912x over previous
#include <cuda_runtime.h>
#include <cuda_fp16.h>
#include <math.h>
#include <stdint.h>

// ---------------- problem constants ----------------
#define Sq   2048
#define Dm   2048
#define Hn   16
#define KVn  4
#define DHd  128
#define En   8
#define Id   1024
#define HD   2048
#define KVD  512
#define EPSf 1e-6f

// ---------------- static device scratch ----------------
__device__ float g_h   [Sq*Dm];
__device__ float g_q   [Sq*HD];
__device__ float g_k   [Sq*KVD];
__device__ float g_v   [Sq*KVD];
__device__ float g_o   [Sq*HD];
__device__ float g_t   [Sq*Dm];
__device__ float g_gate[En*Sq*Id];
__device__ float g_up  [En*Sq*Id];
__device__ float g_moe [2*Sq*Dm];
__device__ int   g_cnt [En];
__device__ int   g_ptok[En*Sq];
__device__ float g_pw  [En*Sq];
__device__ int   g_pslot[En*Sq];

// ---------------- helpers ----------------
__device__ __forceinline__ uint32_t smem_u32(const void* p) {
    uint32_t a;
    asm("{ .reg .u64 t; cvta.to.shared.u64 t, %1; cvt.u32.u64 %0, t; }" : "=r"(a) : "l"(p));
    return a;
}
__device__ __forceinline__ void ldsm4(uint32_t* r, uint32_t a) {
    asm volatile("ldmatrix.sync.aligned.m8n8.x4.shared.b16 {%0,%1,%2,%3}, [%4];"
                 : "=r"(r[0]), "=r"(r[1]), "=r"(r[2]), "=r"(r[3]) : "r"(a));
}
__device__ __forceinline__ void ldsm4t(uint32_t* r, uint32_t a) {
    asm volatile("ldmatrix.sync.aligned.m8n8.x4.trans.shared.b16 {%0,%1,%2,%3}, [%4];"
                 : "=r"(r[0]), "=r"(r[1]), "=r"(r[2]), "=r"(r[3]) : "r"(a));
}
__device__ __forceinline__ void mma16816(float* d, const uint32_t* a, const uint32_t* b) {
    asm volatile("mma.sync.aligned.m16n8k16.row.col.f32.f16.f16.f32 "
                 "{%0,%1,%2,%3}, {%4,%5,%6,%7}, {%8,%9}, {%0,%1,%2,%3};"
                 : "+f"(d[0]), "+f"(d[1]), "+f"(d[2]), "+f"(d[3])
                 : "r"(a[0]), "r"(a[1]), "r"(a[2]), "r"(a[3]), "r"(b[0]), "r"(b[1]));
}

// smem byte offsets (dynamic smem)
#define A_HI_OFF 2048
#define A_LO_OFF 12288                 // A_HI + 128*40*2
#define LDA 40                         // halves per A row (32 + pad)
#define LDB 136                        // halves per B row (128 + pad)
#define A_BYTES 10240                  // 128*40*2
#define B_BYTES 8704                   // 32*136*2

// ---------------- fp16 mma GEMM (optionally hi/lo split) ----------------
// C[M,N] = A[M,K] @ B[K,N]; 128x128x32 tiles, 256 threads (8 warps, 4m x 2n)
template<bool GATHER, bool SCATTER, bool EXPERT, bool RES, bool SPLIT>
__global__ __launch_bounds__(256) void gemm_mma(
    const float* __restrict__ A, const float* __restrict__ Bw,
    float* __restrict__ C, const float* __restrict__ res,
    int M, int N, int K)
{
    extern __shared__ char smem[];
    const int tid = threadIdx.x, lane = tid & 31, wid = tid >> 5;
    const int wm = wid & 3, wn = wid >> 2;
    const int B_HI_OFF = SPLIT ? 22528 : 12288;
    const int B_LO_OFF = 31232;

    int e = 0, cnt = M;
    const float* Aexp = A;
    const float* Bexp = Bw;
    float* Cexp = C;
    if (EXPERT) {
        e = blockIdx.z;
        cnt = g_cnt[e];
        Bexp = Bw + (size_t)e * K * N;
        if (!GATHER) Aexp = A + (size_t)e * Sq * K;
        if (!SCATTER) Cexp = C + (size_t)e * Sq * N;
    }
    const int m0 = blockIdx.y * 128;
    if (EXPERT && m0 >= cnt) return;
    const int n0 = blockIdx.x * 128;

    int*   stok = (int*)smem;
    float* swt  = (float*)(smem + 512);
    int*   ssl  = (int*)(smem + 1024);
    if (GATHER || SCATTER) {
        if (tid < 128) {
            int r = m0 + tid;
            bool ok = r < cnt;
            stok[tid] = ok ? g_ptok[e * Sq + r] : 0;
            if (SCATTER) {
                swt[tid] = ok ? g_pw[e * Sq + r] : 0.f;
                ssl[tid] = ok ? g_pslot[e * Sq + r] : 0;
            }
        }
        __syncthreads();
    }

    const uint32_t sbase = smem_u32(smem);
    const int r_a  = tid >> 1, kb_a = (tid & 1) * 16;   // A: 16 consecutive k
    const int kk_b = tid >> 3, q_b  = tid & 7;          // B: 4 float4 along n

    float4 pa[4], pb[4];

    // prefetch tile it=0
    {
        int grow = GATHER ? stok[r_a] : (m0 + r_a);
        const float4* ap = (const float4*)(Aexp + (size_t)grow * K + kb_a);
        const float*  bp = Bexp + (size_t)kk_b * N + n0;
#pragma unroll
        for (int j = 0; j < 4; j++) pa[j] = ap[j];
#pragma unroll
        for (int j = 0; j < 4; j++) pb[j] = *(const float4*)(bp + (q_b + 8 * j) * 4);
    }

    float acc[2][8][4] = {};
    const int T = K / 32;

    for (int it = 0; it < T; ++it) {
        // ---- stage prefetched regs -> smem (fp16, hi/lo split) ----
        {
            char* pah = smem + A_HI_OFF;
            char* pal = smem + A_LO_OFF;
#pragma unroll
            for (int j = 0; j < 4; j++) {
                float4 v = pa[j];
                half2 h0 = __floats2half2_rn(v.x, v.y);
                half2 h1 = __floats2half2_rn(v.z, v.w);
                int off = (r_a * LDA + kb_a + j * 4) * 2;
                *(half2*)(pah + off)     = h0;
                *(half2*)(pah + off + 4) = h1;
                if (SPLIT) {
                    half2 l0 = __floats2half2_rn(v.x - __low2float(h0), v.y - __high2float(h0));
                    half2 l1 = __floats2half2_rn(v.z - __low2float(h1), v.w - __high2float(h1));
                    *(half2*)(pal + off)     = l0;
                    *(half2*)(pal + off + 4) = l1;
                }
            }
            char* pbh = smem + B_HI_OFF;
            char* pbl = smem + B_LO_OFF;
#pragma unroll
            for (int j = 0; j < 4; j++) {
                float4 v = pb[j];
                half2 h0 = __floats2half2_rn(v.x, v.y);
                half2 h1 = __floats2half2_rn(v.z, v.w);
                int off = (kk_b * LDB + (q_b + 8 * j) * 4) * 2;
                *(half2*)(pbh + off)     = h0;
                *(half2*)(pbh + off + 4) = h1;
                if (SPLIT) {
                    half2 l0 = __floats2half2_rn(v.x - __low2float(h0), v.y - __high2float(h0));
                    half2 l1 = __floats2half2_rn(v.z - __low2float(h1), v.w - __high2float(h1));
                    *(half2*)(pbl + off)     = l0;
                    *(half2*)(pbl + off + 4) = l1;
                }
            }
        }
        __syncthreads();

        // ---- prefetch next tile (LDG latency hidden behind MMAs) ----
        if (it + 1 < T) {
            int k0n = (it + 1) * 32;
            int grow = GATHER ? stok[r_a] : (m0 + r_a);
            const float4* ap = (const float4*)(Aexp + (size_t)grow * K + k0n + kb_a);
            const float*  bp = Bexp + (size_t)(k0n + kk_b) * N + n0;
#pragma unroll
            for (int j = 0; j < 4; j++) pa[j] = ap[j];
#pragma unroll
            for (int j = 0; j < 4; j++) pb[j] = *(const float4*)(bp + (q_b + 8 * j) * 4);
        }

        // ---- tensor-core compute over the staged tile ----
#pragma unroll
        for (int ks = 0; ks < 2; ks++) {
            uint32_t ah[2][4], al[2][4], bh[8][2], bl[8][2];
            int am = wm * 32 + (lane & 7) + ((lane >> 3) & 1) * 8;
            int ak = ks * 16 + (lane >> 4) * 8;
            uint32_t abase = sbase + A_HI_OFF + (am * LDA + ak) * 2;
            ldsm4(ah[0], abase);
            ldsm4(ah[1], abase + 16 * LDA * 2);
            if (SPLIT) {
                ldsm4(al[0], abase + (A_LO_OFF - A_HI_OFF));
                ldsm4(al[1], abase + (A_LO_OFF - A_HI_OFF) + 16 * LDA * 2);
            }
            int bk = ks * 16 + (lane & 7) + ((lane >> 3) & 1) * 8;
            int bn = wn * 64 + (lane >> 4) * 8;
            uint32_t bbase = sbase + B_HI_OFF + (bk * LDB + bn) * 2;
#pragma unroll
            for (int ntp = 0; ntp < 4; ntp++) {
                uint32_t rr[4];
                ldsm4t(rr, bbase + ntp * 32);
                bh[2 * ntp][0] = rr[0]; bh[2 * ntp][1] = rr[1];
                bh[2 * ntp + 1][0] = rr[2]; bh[2 * ntp + 1][1] = rr[3];
                if (SPLIT) {
                    ldsm4t(rr, bbase + (B_LO_OFF - B_HI_OFF) + ntp * 32);
                    bl[2 * ntp][0] = rr[0]; bl[2 * ntp][1] = rr[1];
                    bl[2 * ntp + 1][0] = rr[2]; bl[2 * ntp + 1][1] = rr[3];
                }
            }
#pragma unroll
            for (int mt = 0; mt < 2; mt++)
#pragma unroll
                for (int nt = 0; nt < 8; nt++) {
                    mma16816(acc[mt][nt], ah[mt], bh[nt]);
                    if (SPLIT) {
                        mma16816(acc[mt][nt], ah[mt], bl[nt]);
                        mma16816(acc[mt][nt], al[mt], bh[nt]);
                    }
                }
        }
        __syncthreads();
    }

    // ---- epilogue ----
    const int g = lane >> 2, tig = lane & 3;
#pragma unroll
    for (int mt = 0; mt < 2; mt++) {
#pragma unroll
        for (int hh = 0; hh < 2; hh++) {
            int row = wm * 32 + mt * 16 + g + hh * 8;
            if (EXPERT && m0 + row >= cnt) continue;
            if (SCATTER) {
                int token = stok[row]; float w = swt[row]; int slot = ssl[row];
                float* dst = g_moe + ((size_t)slot * Sq + token) * Dm + n0;
#pragma unroll
                for (int nt = 0; nt < 8; nt++) {
                    int c = wn * 64 + nt * 8 + tig * 2;
                    float2 v = make_float2(w * acc[mt][nt][2 * hh], w * acc[mt][nt][2 * hh + 1]);
                    *(float2*)(dst + c) = v;
                }
            } else {
                float* dst = Cexp + (size_t)(m0 + row) * N + n0;
                const float* rs = RES ? (res + (size_t)(m0 + row) * N + n0) : nullptr;
#pragma unroll
                for (int nt = 0; nt < 8; nt++) {
                    int c = wn * 64 + nt * 8 + tig * 2;
                    float2 v = make_float2(acc[mt][nt][2 * hh], acc[mt][nt][2 * hh + 1]);
                    if (RES) { v.x += rs[c]; v.y += rs[c + 1]; }
                    *(float2*)(dst + c) = v;
                }
            }
        }
    }
}

#define SMEM_SPLIT 39936
#define SMEM_SINGLE 20992

// ---------------- rmsnorm ----------------
__global__ __launch_bounds__(256) void rmsnorm_k(const float* __restrict__ in,
                                                 const float* __restrict__ w,
                                                 float* __restrict__ out, int cols) {
    int row = blockIdx.x;
    const float* r = in + (size_t)row * cols;
    float ss = 0.f;
    for (int i = threadIdx.x; i < cols; i += 256) { float v = r[i]; ss += v * v; }
    __shared__ float red[256];
    red[threadIdx.x] = ss; __syncthreads();
    for (int st = 128; st > 0; st >>= 1) {
        if (threadIdx.x < st) red[threadIdx.x] += red[threadIdx.x + st];
        __syncthreads();
    }
    float scale = rsqrtf(red[0] / (float)cols + EPSf);
    for (int i = threadIdx.x; i < cols; i += 256)
        out[(size_t)row * cols + i] = r[i] * scale * w[i];
}

// ---------------- RoPE ----------------
__global__ __launch_bounds__(256) void rope_k(float* __restrict__ q, int nheads) {
    int idx = blockIdx.x * 256 + threadIdx.x;
    int d = idx & 31;
    int h = (idx >> 5) % nheads;
    int s = idx / (32 * nheads);
    float inv = powf(1.0e6f, -(float)d / 32.f);
    float ang = (float)s * inv;
    float c = cosf(ang), sn = sinf(ang);
    float* base = q + (size_t)s * (nheads * DHd) + h * DHd;
    float x1 = base[d], x2 = base[d + 32];
    base[d]      = x1 * c - x2 * sn;
    base[d + 32] = x2 * c + x1 * sn;
}

// ---------------- flash attention (fp32, causal, GQA) ----------------
__global__ __launch_bounds__(256) void attn_k(const float* __restrict__ q,
                                              const float* __restrict__ k,
                                              const float* __restrict__ v,
                                              float* __restrict__ o) {
    extern __shared__ float sm[];
    float* Qs = sm;
    float* Ks = Qs + 64 * 129;
    float* Vs = Ks + 64 * 129;
    float* Ps = Vs + 64 * 128;
    float* Mrow = Ps + 64 * 65;
    float* Lrow = Mrow + 64;
    int qb = gridDim.x - 1 - blockIdx.x;
    int h  = blockIdx.y;
    int kvh = h >> 2;
    int tid = threadIdx.x, tx = tid & 15, ty = tid >> 4;
    const float scale = 0.08838834764831845f;

    for (int i = tid; i < 64 * 128; i += 256) {
        int r = i >> 7, c = i & 127;
        Qs[r * 129 + c] = q[(size_t)(qb * 64 + r) * HD + h * DHd + c];
    }
    if (tid < 64) { Mrow[tid] = -INFINITY; Lrow[tid] = 0.f; }
    float accO[4][8] = {};

    for (int kb = 0; kb <= qb; kb++) {
        for (int i = tid; i < 64 * 128; i += 256) {
            int r = i >> 7, c = i & 127;
            size_t src = (size_t)(kb * 64 + r) * KVD + kvh * DHd + c;
            Ks[r * 129 + c] = k[src];
            Vs[r * 128 + c] = v[src];
        }
        __syncthreads();

        float sc[4][4] = {};
#pragma unroll 4
        for (int kk = 0; kk < 128; kk++) {
            float a[4], b[4];
#pragma unroll
            for (int i = 0; i < 4; i++) a[i] = Qs[(ty * 4 + i) * 129 + kk];
#pragma unroll
            for (int j = 0; j < 4; j++) b[j] = Ks[(tx * 4 + j) * 129 + kk];
#pragma unroll
            for (int i = 0; i < 4; i++)
#pragma unroll
                for (int j = 0; j < 4; j++) sc[i][j] += a[i] * b[j];
        }
#pragma unroll
        for (int i = 0; i < 4; i++) {
            int qrow = qb * 64 + ty * 4 + i;
#pragma unroll
            for (int j = 0; j < 4; j++) {
                int kcol = kb * 64 + tx * 4 + j;
                sc[i][j] = (kcol <= qrow) ? sc[i][j] * scale : -INFINITY;
            }
        }
#pragma unroll
        for (int i = 0; i < 4; i++) {
            int row = ty * 4 + i;
            float mloc = -INFINITY;
#pragma unroll
            for (int j = 0; j < 4; j++) mloc = fmaxf(mloc, sc[i][j]);
            for (int off = 8; off > 0; off >>= 1)
                mloc = fmaxf(mloc, __shfl_xor_sync(0xffffffffu, mloc, off));
            float mold = Mrow[row];
            float mnew = fmaxf(mold, mloc);
            float alpha = expf(mold - mnew);
            float ls = 0.f;
#pragma unroll
            for (int j = 0; j < 4; j++) {
                float p = expf(sc[i][j] - mnew);
                Ps[row * 65 + tx * 4 + j] = p;
                ls += p;
            }
            for (int off = 8; off > 0; off >>= 1)
                ls += __shfl_xor_sync(0xffffffffu, ls, off);
#pragma unroll
            for (int c = 0; c < 8; c++) accO[i][c] *= alpha;
            if (tx == 0) { Mrow[row] = mnew; Lrow[row] = Lrow[row] * alpha + ls; }
        }
        __syncthreads();

#pragma unroll 4
        for (int kk = 0; kk < 64; kk++) {
            float a[4];
#pragma unroll
            for (int i = 0; i < 4; i++) a[i] = Ps[(ty * 4 + i) * 65 + kk];
            float4 v0 = *(const float4*)&Vs[kk * 128 + tx * 8];
            float4 v1 = *(const float4*)&Vs[kk * 128 + tx * 8 + 4];
#pragma unroll
            for (int i = 0; i < 4; i++) {
                accO[i][0] += a[i] * v0.x; accO[i][1] += a[i] * v0.y;
                accO[i][2] += a[i] * v0.z; accO[i][3] += a[i] * v0.w;
                accO[i][4] += a[i] * v1.x; accO[i][5] += a[i] * v1.y;
                accO[i][6] += a[i] * v1.z; accO[i][7] += a[i] * v1.w;
            }
        }
        __syncthreads();
    }
#pragma unroll
    for (int i = 0; i < 4; i++) {
        int row = ty * 4 + i;
        float inv = 1.f / Lrow[row];
#pragma unroll
        for (int j = 0; j < 8; j++)
            o[(size_t)(qb * 64 + row) * HD + h * DHd + tx * 8 + j] = accO[i][j] * inv;
    }
}

// ---------------- router ----------------
__global__ __launch_bounds__(256) void reset_k() {
    if (threadIdx.x < En) g_cnt[threadIdx.x] = 0;
}

__global__ __launch_bounds__(256) void router_k(const float* __restrict__ Tm,
                                                const float* __restrict__ rw,
                                                const float* __restrict__ rb) {
    int row = blockIdx.x, tid = threadIdx.x;
    const float* r = Tm + (size_t)row * Dm;
    float loc[En] = {};
    for (int d = tid; d < Dm; d += 256) {
        float x = r[d];
#pragma unroll
        for (int e = 0; e < En; e++) loc[e] += x * rw[d * En + e];
    }
    __shared__ float sred[256 * En];
#pragma unroll
    for (int e = 0; e < En; e++) sred[tid * En + e] = loc[e];
    __syncthreads();
    for (int st = 128; st > 0; st >>= 1) {
        if (tid < st)
#pragma unroll
            for (int e = 0; e < En; e++) sred[tid * En + e] += sred[(tid + st) * En + e];
        __syncthreads();
    }
    if (tid == 0) {
        float sig[En], scv[En];
#pragma unroll
        for (int e = 0; e < En; e++) {
            float l = sred[e];
            sig[e] = 1.f / (1.f + expf(-l));
            scv[e] = sig[e] + rb[e];
        }
        int i0 = 0;
#pragma unroll
        for (int e = 1; e < En; e++) if (scv[e] > scv[i0]) i0 = e;
        int i1 = -1;
#pragma unroll
        for (int e = 0; e < En; e++)
            if (e != i0 && (i1 < 0 || scv[e] > scv[i1])) i1 = e;
        float a0 = sig[i0], a1 = sig[i1], s = a0 + a1;
        float w0 = a0 / s, w1 = a1 / s;
        int p = atomicAdd(&g_cnt[i0], 1);
        g_ptok[i0 * Sq + p] = row; g_pw[i0 * Sq + p] = w0; g_pslot[i0 * Sq + p] = 0;
        p = atomicAdd(&g_cnt[i1], 1);
        g_ptok[i1 * Sq + p] = row; g_pw[i1 * Sq + p] = w1; g_pslot[i1 * Sq + p] = 1;
    }
}

// ---------------- act = silu(gate)*up ----------------
__global__ __launch_bounds__(256) void act_k() {
    int e = blockIdx.z;
    int cnt = g_cnt[e];
    int i = blockIdx.x * 256 + threadIdx.x;
    int row = i >> 10;
    if (row >= cnt) return;
    size_t idx = (size_t)e * Sq * Id + i;
    float g = g_gate[idx];
    float u = g_up[idx];
    g_gate[idx] = (g / (1.f + expf(-g))) * u;
}

// ---------------- final: out = x1 + moe0 + moe1 ----------------
__global__ __launch_bounds__(256) void final_add_k(float* __restrict__ out) {
    int i = blockIdx.x * 256 + threadIdx.x;
    out[i] = out[i] + g_moe[i] + g_moe[(size_t)Sq * Dm + i];
}

// ---------------- host orchestration ----------------
extern "C" void kernel_launch(void* const* d_in, const int* in_sizes, int n_in,
                              void* d_out, int out_size) {
    const float* x    = (const float*)d_in[0];
    const float* ln1  = (const float*)d_in[1];
    const float* ln2  = (const float*)d_in[2];
    const float* wq   = (const float*)d_in[3];
    const float* wk   = (const float*)d_in[4];
    const float* wv   = (const float*)d_in[5];
    const float* wo   = (const float*)d_in[6];
    const float* qn   = (const float*)d_in[7];
    const float* kn   = (const float*)d_in[8];
    const float* rw   = (const float*)d_in[9];
    const float* rb   = (const float*)d_in[10];
    const float* wg   = (const float*)d_in[11];
    const float* wu   = (const float*)d_in[12];
    const float* wd   = (const float*)d_in[13];
    float* out = (float*)d_out;

    float *ph, *pq, *pk, *pv, *po, *pt, *pgate, *pup;
    cudaGetSymbolAddress((void**)&ph,    g_h);
    cudaGetSymbolAddress((void**)&pq,    g_q);
    cudaGetSymbolAddress((void**)&pk,    g_k);
    cudaGetSymbolAddress((void**)&pv,    g_v);
    cudaGetSymbolAddress((void**)&po,    g_o);
    cudaGetSymbolAddress((void**)&pt,    g_t);
    cudaGetSymbolAddress((void**)&pgate, g_gate);
    cudaGetSymbolAddress((void**)&pup,   g_up);

    int attn_smem = (64 * 129 * 2 + 64 * 128 + 64 * 65 + 128) * 4;
    cudaFuncSetAttribute(attn_k, cudaFuncAttributeMaxDynamicSharedMemorySize, attn_smem);

    // 1. h = rmsnorm(x, ln1)
    rmsnorm_k<<<Sq, 256>>>(x, ln1, ph, Dm);
    // 2. q,k,v projections (fp16 split mma)
    gemm_mma<false,false,false,false,true><<<dim3(HD/128,  Sq/128), 256, SMEM_SPLIT>>>(ph, wq, pq, nullptr, Sq, HD, Dm);
    gemm_mma<false,false,false,false,true><<<dim3(KVD/128, Sq/128), 256, SMEM_SPLIT>>>(ph, wk, pk, nullptr, Sq, KVD, Dm);
    gemm_mma<false,false,false,false,true><<<dim3(KVD/128, Sq/128), 256, SMEM_SPLIT>>>(ph, wv, pv, nullptr, Sq, KVD, Dm);
    // 3. q/k rmsnorm
    rmsnorm_k<<<Sq, 256>>>(pq, qn, pq, HD);
    rmsnorm_k<<<Sq, 256>>>(pk, kn, pk, KVD);
    // 4. RoPE
    rope_k<<<(Sq * Hn * 32) / 256, 256>>>(pq, Hn);
    rope_k<<<(Sq * KVn * 32) / 256, 256>>>(pk, KVn);
    // 5. attention (fp32 SIMT)
    attn_k<<<dim3(Sq / 64, Hn), 256, attn_smem>>>(pq, pk, pv, po);
    // 6. x1 = x + o @ wo (fp16 split mma)
    gemm_mma<false,false,false,true,true><<<dim3(Dm/128, Sq/128), 256, SMEM_SPLIT>>>(po, wo, out, x, Sq, Dm, HD);
    // 7. t = rmsnorm(x1, ln2)
    rmsnorm_k<<<Sq, 256>>>(out, ln2, pt, Dm);
    // 8. routing
    reset_k<<<1, 256>>>();
    router_k<<<Sq, 256>>>(pt, rw, rb);
    // 9. expert gate/up (gathered, single fp16 mma)
    gemm_mma<true,false,true,false,false><<<dim3(Id/128, Sq/128, En), 256, SMEM_SINGLE>>>(pt, wg, pgate, nullptr, Sq, Id, Dm);
    gemm_mma<true,false,true,false,false><<<dim3(Id/128, Sq/128, En), 256, SMEM_SINGLE>>>(pt, wu, pup, nullptr, Sq, Id, Dm);
    // 10. act
    act_k<<<dim3((Sq * Id) / 256, 1, En), 256>>>();
    // 11. down GEMM + weighted scatter (single fp16 mma)
    gemm_mma<false,true,true,false,false><<<dim3(Dm/128, Sq/128, En), 256, SMEM_SINGLE>>>(pgate, wd, nullptr, nullptr, Sq, Dm, Id);
    // 12. out = x1 + moe
    final_add_k<<<(Sq * Dm) / 256, 256>>>(out);
}

// round 5
// speedup vs baseline: 4.0118x; 1.5207x over previous
#include <cuda_runtime.h>
#include <cuda_fp16.h>
#include <math.h>
#include <stdint.h>

// ---------------- problem constants ----------------
#define Sq   2048
#define Dm   2048
#define Hn   16
#define KVn  4
#define DHd  128
#define En   8
#define Id   1024
#define HD   2048
#define KVD  512
#define EPSf 1e-6f

// ---------------- static device scratch ----------------
__device__ float g_h   [Sq*Dm];
__device__ float g_q   [Sq*HD];
__device__ float g_k   [Sq*KVD];
__device__ float g_v   [Sq*KVD];
__device__ float g_o   [Sq*HD];
__device__ float g_t   [Sq*Dm];
__device__ float g_gate[En*Sq*Id];
__device__ float g_up  [En*Sq*Id];
__device__ float g_moe [2*Sq*Dm];
__device__ int   g_cnt [En];
__device__ int   g_ptok[En*Sq];
__device__ float g_pw  [En*Sq];
__device__ int   g_pslot[En*Sq];

// ---------------- helpers ----------------
__device__ __forceinline__ uint32_t smem_u32(const void* p) {
    uint32_t a;
    asm("{ .reg .u64 t; cvta.to.shared.u64 t, %1; cvt.u32.u64 %0, t; }" : "=r"(a) : "l"(p));
    return a;
}
__device__ __forceinline__ void ldsm4(uint32_t* r, uint32_t a) {
    asm volatile("ldmatrix.sync.aligned.m8n8.x4.shared.b16 {%0,%1,%2,%3}, [%4];"
                 : "=r"(r[0]), "=r"(r[1]), "=r"(r[2]), "=r"(r[3]) : "r"(a));
}
__device__ __forceinline__ void ldsm4t(uint32_t* r, uint32_t a) {
    asm volatile("ldmatrix.sync.aligned.m8n8.x4.trans.shared.b16 {%0,%1,%2,%3}, [%4];"
                 : "=r"(r[0]), "=r"(r[1]), "=r"(r[2]), "=r"(r[3]) : "r"(a));
}
__device__ __forceinline__ void mma16816(float* d, const uint32_t* a, const uint32_t* b) {
    asm volatile("mma.sync.aligned.m16n8k16.row.col.f32.f16.f16.f32 "
                 "{%0,%1,%2,%3}, {%4,%5,%6,%7}, {%8,%9}, {%0,%1,%2,%3};"
                 : "+f"(d[0]), "+f"(d[1]), "+f"(d[2]), "+f"(d[3])
                 : "r"(a[0]), "r"(a[1]), "r"(a[2]), "r"(a[3]), "r"(b[0]), "r"(b[1]));
}
__device__ __forceinline__ void split2(float x, float y, half2& hi, half2& lo) {
    hi = __floats2half2_rn(x, y);
    lo = __floats2half2_rn(x - __low2float(hi), y - __high2float(hi));
}

// ================= fp16 mma GEMM (optionally hi/lo split) =================
#define A_HI_OFF 2048
#define A_LO_OFF 12288
#define LDA 40
#define LDB 136

template<bool GATHER, bool SCATTER, bool EXPERT, bool RES, bool SPLIT>
__global__ __launch_bounds__(256) void gemm_mma(
    const float* __restrict__ A, const float* __restrict__ Bw,
    float* __restrict__ C, const float* __restrict__ res,
    int M, int N, int K)
{
    extern __shared__ char smem[];
    const int tid = threadIdx.x, lane = tid & 31, wid = tid >> 5;
    const int wm = wid & 3, wn = wid >> 2;
    const int B_HI_OFF = SPLIT ? 22528 : 12288;
    const int B_LO_OFF = 31232;

    int e = 0, cnt = M;
    const float* Aexp = A;
    const float* Bexp = Bw;
    float* Cexp = C;
    if (EXPERT) {
        e = blockIdx.z;
        cnt = g_cnt[e];
        Bexp = Bw + (size_t)e * K * N;
        if (!GATHER) Aexp = A + (size_t)e * Sq * K;
        if (!SCATTER) Cexp = C + (size_t)e * Sq * N;
    }
    const int m0 = blockIdx.y * 128;
    if (EXPERT && m0 >= cnt) return;
    const int n0 = blockIdx.x * 128;

    int*   stok = (int*)smem;
    float* swt  = (float*)(smem + 512);
    int*   ssl  = (int*)(smem + 1024);
    if (GATHER || SCATTER) {
        if (tid < 128) {
            int r = m0 + tid;
            bool ok = r < cnt;
            stok[tid] = ok ? g_ptok[e * Sq + r] : 0;
            if (SCATTER) {
                swt[tid] = ok ? g_pw[e * Sq + r] : 0.f;
                ssl[tid] = ok ? g_pslot[e * Sq + r] : 0;
            }
        }
        __syncthreads();
    }

    const uint32_t sbase = smem_u32(smem);
    const int r_a  = tid >> 1, kb_a = (tid & 1) * 16;
    const int kk_b = tid >> 3, q_b  = tid & 7;

    float4 pa[4], pb[4];
    {
        int grow = GATHER ? stok[r_a] : (m0 + r_a);
        const float4* ap = (const float4*)(Aexp + (size_t)grow * K + kb_a);
        const float*  bp = Bexp + (size_t)kk_b * N + n0;
#pragma unroll
        for (int j = 0; j < 4; j++) pa[j] = ap[j];
#pragma unroll
        for (int j = 0; j < 4; j++) pb[j] = *(const float4*)(bp + (q_b + 8 * j) * 4);
    }

    float acc[2][8][4] = {};
    const int T = K / 32;

    for (int it = 0; it < T; ++it) {
        {
            char* pah = smem + A_HI_OFF;
            char* pal = smem + A_LO_OFF;
#pragma unroll
            for (int j = 0; j < 4; j++) {
                float4 v = pa[j];
                half2 h0, l0, h1, l1;
                split2(v.x, v.y, h0, l0); split2(v.z, v.w, h1, l1);
                int off = (r_a * LDA + kb_a + j * 4) * 2;
                *(half2*)(pah + off)     = h0;
                *(half2*)(pah + off + 4) = h1;
                if (SPLIT) { *(half2*)(pal + off) = l0; *(half2*)(pal + off + 4) = l1; }
            }
            char* pbh = smem + B_HI_OFF;
            char* pbl = smem + B_LO_OFF;
#pragma unroll
            for (int j = 0; j < 4; j++) {
                float4 v = pb[j];
                half2 h0, l0, h1, l1;
                split2(v.x, v.y, h0, l0); split2(v.z, v.w, h1, l1);
                int off = (kk_b * LDB + (q_b + 8 * j) * 4) * 2;
                *(half2*)(pbh + off)     = h0;
                *(half2*)(pbh + off + 4) = h1;
                if (SPLIT) { *(half2*)(pbl + off) = l0; *(half2*)(pbl + off + 4) = l1; }
            }
        }
        __syncthreads();

        if (it + 1 < T) {
            int k0n = (it + 1) * 32;
            int grow = GATHER ? stok[r_a] : (m0 + r_a);
            const float4* ap = (const float4*)(Aexp + (size_t)grow * K + k0n + kb_a);
            const float*  bp = Bexp + (size_t)(k0n + kk_b) * N + n0;
#pragma unroll
            for (int j = 0; j < 4; j++) pa[j] = ap[j];
#pragma unroll
            for (int j = 0; j < 4; j++) pb[j] = *(const float4*)(bp + (q_b + 8 * j) * 4);
        }

#pragma unroll
        for (int ks = 0; ks < 2; ks++) {
            uint32_t ah[2][4], al[2][4], bh[8][2], bl[8][2];
            int am = wm * 32 + (lane & 7) + ((lane >> 3) & 1) * 8;
            int ak = ks * 16 + (lane >> 4) * 8;
            uint32_t abase = sbase + A_HI_OFF + (am * LDA + ak) * 2;
            ldsm4(ah[0], abase);
            ldsm4(ah[1], abase + 16 * LDA * 2);
            if (SPLIT) {
                ldsm4(al[0], abase + (A_LO_OFF - A_HI_OFF));
                ldsm4(al[1], abase + (A_LO_OFF - A_HI_OFF) + 16 * LDA * 2);
            }
            int bk = ks * 16 + (lane & 7) + ((lane >> 3) & 1) * 8;
            int bn = wn * 64 + (lane >> 4) * 8;
            uint32_t bbase = sbase + B_HI_OFF + (bk * LDB + bn) * 2;
#pragma unroll
            for (int ntp = 0; ntp < 4; ntp++) {
                uint32_t rr[4];
                ldsm4t(rr, bbase + ntp * 32);
                bh[2 * ntp][0] = rr[0]; bh[2 * ntp][1] = rr[1];
                bh[2 * ntp + 1][0] = rr[2]; bh[2 * ntp + 1][1] = rr[3];
                if (SPLIT) {
                    ldsm4t(rr, bbase + (B_LO_OFF - B_HI_OFF) + ntp * 32);
                    bl[2 * ntp][0] = rr[0]; bl[2 * ntp][1] = rr[1];
                    bl[2 * ntp + 1][0] = rr[2]; bl[2 * ntp + 1][1] = rr[3];
                }
            }
#pragma unroll
            for (int mt = 0; mt < 2; mt++)
#pragma unroll
                for (int nt = 0; nt < 8; nt++) {
                    mma16816(acc[mt][nt], ah[mt], bh[nt]);
                    if (SPLIT) {
                        mma16816(acc[mt][nt], ah[mt], bl[nt]);
                        mma16816(acc[mt][nt], al[mt], bh[nt]);
                    }
                }
        }
        __syncthreads();
    }

    const int g = lane >> 2, tig = lane & 3;
#pragma unroll
    for (int mt = 0; mt < 2; mt++) {
#pragma unroll
        for (int hh = 0; hh < 2; hh++) {
            int row = wm * 32 + mt * 16 + g + hh * 8;
            if (EXPERT && m0 + row >= cnt) continue;
            if (SCATTER) {
                int token = stok[row]; float w = swt[row]; int slot = ssl[row];
                float* dst = g_moe + ((size_t)slot * Sq + token) * Dm + n0;
#pragma unroll
                for (int nt = 0; nt < 8; nt++) {
                    int c = wn * 64 + nt * 8 + tig * 2;
                    float2 v = make_float2(w * acc[mt][nt][2 * hh], w * acc[mt][nt][2 * hh + 1]);
                    *(float2*)(dst + c) = v;
                }
            } else {
                float* dst = Cexp + (size_t)(m0 + row) * N + n0;
                const float* rs = RES ? (res + (size_t)(m0 + row) * N + n0) : nullptr;
#pragma unroll
                for (int nt = 0; nt < 8; nt++) {
                    int c = wn * 64 + nt * 8 + tig * 2;
                    float2 v = make_float2(acc[mt][nt][2 * hh], acc[mt][nt][2 * hh + 1]);
                    if (RES) { v.x += rs[c]; v.y += rs[c + 1]; }
                    *(float2*)(dst + c) = v;
                }
            }
        }
    }
}

#define SMEM_SPLIT 39936
#define SMEM_SINGLE 20992

// ================= tensor-core flash attention (fp16 split, causal, GQA) =================
// block = (128 q rows, 1 head); 8 warps: wm=wid&3 (32 rows), wn=wid>>2.
#define QH_O 0
#define QL_O 34816
#define KH_O 69632
#define KL_O 87040
#define VH_O 104448
#define VL_O 121856
#define PH_O 139264
#define PL_O 157696
#define MAXB_O 176128
#define SUMB_O 177152
#define MROW_O 178176
#define LROW_O 178688
#define ATT_SMEM 179200
#define LDQ 136
#define LDP 72

__global__ __launch_bounds__(256) void attn_mma(const float* __restrict__ q,
                                                const float* __restrict__ k,
                                                const float* __restrict__ v,
                                                float* __restrict__ o) {
    extern __shared__ char smem[];
    const uint32_t sb = smem_u32(smem);
    const int qb = gridDim.x - 1 - blockIdx.x;
    const int h = blockIdx.y, kvh = h >> 2;
    const int tid = threadIdx.x, lane = tid & 31, wid = tid >> 5;
    const int wm = wid & 3, wn = wid >> 2;
    float* Mrow = (float*)(smem + MROW_O);
    float* Lrow = (float*)(smem + LROW_O);
    float* maxb = (float*)(smem + MAXB_O);
    float* sumb = (float*)(smem + SUMB_O);

    // ---- stage Q (pre-scaled) hi/lo ----
    const float scale = 0.08838834764831845f;  // 1/sqrt(128)
#pragma unroll
    for (int j = 0; j < 16; j++) {
        int idx = tid + j * 256;            // 4096 float4
        int r = idx >> 5, c4 = idx & 31;
        float4 vv = *(const float4*)&q[(size_t)(qb * 128 + r) * HD + h * DHd + c4 * 4];
        vv.x *= scale; vv.y *= scale; vv.z *= scale; vv.w *= scale;
        half2 h0, l0, h1, l1;
        split2(vv.x, vv.y, h0, l0); split2(vv.z, vv.w, h1, l1);
        int off = (r * LDQ + c4 * 4) * 2;
        *(half2*)(smem + QH_O + off)     = h0;
        *(half2*)(smem + QH_O + off + 4) = h1;
        *(half2*)(smem + QL_O + off)     = l0;
        *(half2*)(smem + QL_O + off + 4) = l1;
    }
    if (tid < 128) { Mrow[tid] = -INFINITY; Lrow[tid] = 0.f; }

    float oacc[2][8][4] = {};
    const int g = lane >> 2, tig = lane & 3;

    for (int kbg = 0; kbg <= 2 * qb + 1; kbg++) {
        __syncthreads();   // protect K/V/P reuse (and Q staging on first iter)

        // ---- stage K,V tile (64 x 128) hi/lo ----
#pragma unroll
        for (int j = 0; j < 8; j++) {
            int idx = tid + j * 256;        // 2048 float4
            int r = idx >> 5, c4 = idx & 31;
            size_t src = (size_t)(kbg * 64 + r) * KVD + kvh * DHd + c4 * 4;
            int off = (r * LDQ + c4 * 4) * 2;
            float4 kv4 = *(const float4*)&k[src];
            half2 h0, l0, h1, l1;
            split2(kv4.x, kv4.y, h0, l0); split2(kv4.z, kv4.w, h1, l1);
            *(half2*)(smem + KH_O + off)     = h0;
            *(half2*)(smem + KH_O + off + 4) = h1;
            *(half2*)(smem + KL_O + off)     = l0;
            *(half2*)(smem + KL_O + off + 4) = l1;
            float4 vv4 = *(const float4*)&v[src];
            split2(vv4.x, vv4.y, h0, l0); split2(vv4.z, vv4.w, h1, l1);
            *(half2*)(smem + VH_O + off)     = h0;
            *(half2*)(smem + VH_O + off + 4) = h1;
            *(half2*)(smem + VL_O + off)     = l0;
            *(half2*)(smem + VL_O + off + 4) = l1;
        }
        __syncthreads();

        // ---- S = Q @ K^T (split) ----
        float sacc[2][4][4] = {};
        const int arow = wm * 32 + (lane & 7) + ((lane >> 3) & 1) * 8;
        const int brow = wn * 32 + (lane & 7) + 8 * (lane >> 4);
#pragma unroll
        for (int ks = 0; ks < 8; ks++) {
            uint32_t ah[2][4], al[2][4], bh[4][2], bl[4][2];
            int ak = ks * 16 + (lane >> 4) * 8;
            uint32_t ab = sb + QH_O + (arow * LDQ + ak) * 2;
            ldsm4(ah[0], ab);
            ldsm4(ah[1], ab + 16 * LDQ * 2);
            ldsm4(al[0], ab + (QL_O - QH_O));
            ldsm4(al[1], ab + (QL_O - QH_O) + 16 * LDQ * 2);
            int bk = ks * 16 + ((lane >> 3) & 1) * 8;
#pragma unroll
            for (int t = 0; t < 2; t++) {
                uint32_t rr[4];
                uint32_t bb = sb + KH_O + ((brow + t * 16) * LDQ + bk) * 2;
                ldsm4(rr, bb);
                bh[2 * t][0] = rr[0]; bh[2 * t][1] = rr[1];
                bh[2 * t + 1][0] = rr[2]; bh[2 * t + 1][1] = rr[3];
                ldsm4(rr, bb + (KL_O - KH_O));
                bl[2 * t][0] = rr[0]; bl[2 * t][1] = rr[1];
                bl[2 * t + 1][0] = rr[2]; bl[2 * t + 1][1] = rr[3];
            }
#pragma unroll
            for (int mt = 0; mt < 2; mt++)
#pragma unroll
                for (int nf = 0; nf < 4; nf++) {
                    mma16816(sacc[mt][nf], ah[mt], bh[nf]);
                    mma16816(sacc[mt][nf], ah[mt], bl[nf]);
                    mma16816(sacc[mt][nf], al[mt], bh[nf]);
                }
        }

        // ---- causal mask (diagonal blocks only) ----
        if (kbg >= 2 * qb) {
#pragma unroll
            for (int mt = 0; mt < 2; mt++)
#pragma unroll
                for (int nf = 0; nf < 4; nf++)
#pragma unroll
                    for (int i = 0; i < 4; i++) {
                        int row = qb * 128 + wm * 32 + mt * 16 + g + (i >= 2 ? 8 : 0);
                        int col = kbg * 64 + wn * 32 + nf * 8 + tig * 2 + (i & 1);
                        if (col > row) sacc[mt][nf][i] = -INFINITY;
                    }
        }

        // ---- local row max -> maxb ----
        float rmax[2][2];
#pragma unroll
        for (int mt = 0; mt < 2; mt++)
#pragma unroll
            for (int hh = 0; hh < 2; hh++) {
                float m = -INFINITY;
#pragma unroll
                for (int nf = 0; nf < 4; nf++)
                    m = fmaxf(m, fmaxf(sacc[mt][nf][2 * hh], sacc[mt][nf][2 * hh + 1]));
                m = fmaxf(m, __shfl_xor_sync(0xffffffffu, m, 1));
                m = fmaxf(m, __shfl_xor_sync(0xffffffffu, m, 2));
                rmax[mt][hh] = m;
            }
        if (tig == 0) {
#pragma unroll
            for (int mt = 0; mt < 2; mt++) {
                int r = wm * 32 + mt * 16 + g;
                maxb[wn * 128 + r] = rmax[mt][0];
                maxb[wn * 128 + r + 8] = rmax[mt][1];
            }
        }
        __syncthreads();

        // ---- mnew/alpha, exp, P store (hi/lo), row sums, O rescale ----
        float alpha[2][2], mnew[2][2], rsum[2][2];
#pragma unroll
        for (int mt = 0; mt < 2; mt++)
#pragma unroll
            for (int hh = 0; hh < 2; hh++) {
                int r = wm * 32 + mt * 16 + g + hh * 8;
                float mo = Mrow[r];
                float mn = fmaxf(mo, fmaxf(maxb[r], maxb[128 + r]));
                mnew[mt][hh] = mn;
                alpha[mt][hh] = expf(mo - mn);
                rsum[mt][hh] = 0.f;
            }
#pragma unroll
        for (int mt = 0; mt < 2; mt++)
#pragma unroll
            for (int nf = 0; nf < 4; nf++) {
#pragma unroll
                for (int hh = 0; hh < 2; hh++) {
                    float p0 = expf(sacc[mt][nf][2 * hh]     - mnew[mt][hh]);
                    float p1 = expf(sacc[mt][nf][2 * hh + 1] - mnew[mt][hh]);
                    rsum[mt][hh] += p0 + p1;
                    half2 hi, lo;
                    split2(p0, p1, hi, lo);
                    int r = wm * 32 + mt * 16 + g + hh * 8;
                    int c = wn * 32 + nf * 8 + tig * 2;
                    *(half2*)(smem + PH_O + (r * LDP + c) * 2) = hi;
                    *(half2*)(smem + PL_O + (r * LDP + c) * 2) = lo;
                }
            }
#pragma unroll
        for (int mt = 0; mt < 2; mt++)
#pragma unroll
            for (int hh = 0; hh < 2; hh++) {
                float s = rsum[mt][hh];
                s += __shfl_xor_sync(0xffffffffu, s, 1);
                s += __shfl_xor_sync(0xffffffffu, s, 2);
                rsum[mt][hh] = s;
            }
        if (tig == 0) {
#pragma unroll
            for (int mt = 0; mt < 2; mt++) {
                int r = wm * 32 + mt * 16 + g;
                sumb[wn * 128 + r] = rsum[mt][0];
                sumb[wn * 128 + r + 8] = rsum[mt][1];
            }
        }
        // rescale O accumulators
#pragma unroll
        for (int mt = 0; mt < 2; mt++)
#pragma unroll
            for (int nf = 0; nf < 8; nf++) {
                oacc[mt][nf][0] *= alpha[mt][0]; oacc[mt][nf][1] *= alpha[mt][0];
                oacc[mt][nf][2] *= alpha[mt][1]; oacc[mt][nf][3] *= alpha[mt][1];
            }
        __syncthreads();

        // ---- update row stats (one n-warp) ----
        if (wn == 0 && tig == 0) {
#pragma unroll
            for (int mt = 0; mt < 2; mt++)
#pragma unroll
                for (int hh = 0; hh < 2; hh++) {
                    int r = wm * 32 + mt * 16 + g + hh * 8;
                    Lrow[r] = Lrow[r] * alpha[mt][hh] + sumb[r] + sumb[128 + r];
                    Mrow[r] = mnew[mt][hh];
                }
        }

        // ---- O += P @ V (split) ----
#pragma unroll
        for (int ks = 0; ks < 4; ks++) {
            uint32_t ph[2][4], pl[2][4], vh[8][2], vl[8][2];
            int ak = ks * 16 + (lane >> 4) * 8;
            uint32_t ab = sb + PH_O + (arow * LDP + ak) * 2;
            ldsm4(ph[0], ab);
            ldsm4(ph[1], ab + 16 * LDP * 2);
            ldsm4(pl[0], ab + (PL_O - PH_O));
            ldsm4(pl[1], ab + (PL_O - PH_O) + 16 * LDP * 2);
            int vk = ks * 16 + (lane & 7) + ((lane >> 3) & 1) * 8;
            int vn = wn * 64 + (lane >> 4) * 8;
            uint32_t vb = sb + VH_O + (vk * LDQ + vn) * 2;
#pragma unroll
            for (int ntp = 0; ntp < 4; ntp++) {
                uint32_t rr[4];
                ldsm4t(rr, vb + ntp * 32);
                vh[2 * ntp][0] = rr[0]; vh[2 * ntp][1] = rr[1];
                vh[2 * ntp + 1][0] = rr[2]; vh[2 * ntp + 1][1] = rr[3];
                ldsm4t(rr, vb + (VL_O - VH_O) + ntp * 32);
                vl[2 * ntp][0] = rr[0]; vl[2 * ntp][1] = rr[1];
                vl[2 * ntp + 1][0] = rr[2]; vl[2 * ntp + 1][1] = rr[3];
            }
#pragma unroll
            for (int mt = 0; mt < 2; mt++)
#pragma unroll
                for (int nf = 0; nf < 8; nf++) {
                    mma16816(oacc[mt][nf], ph[mt], vh[nf]);
                    mma16816(oacc[mt][nf], ph[mt], vl[nf]);
                    mma16816(oacc[mt][nf], pl[mt], vh[nf]);
                }
        }
    }

    __syncthreads();
    // ---- epilogue ----
#pragma unroll
    for (int mt = 0; mt < 2; mt++)
#pragma unroll
        for (int hh = 0; hh < 2; hh++) {
            int r = wm * 32 + mt * 16 + g + hh * 8;
            float inv = 1.f / Lrow[r];
#pragma unroll
            for (int nf = 0; nf < 8; nf++) {
                int c = wn * 64 + nf * 8 + tig * 2;
                float2 val = make_float2(oacc[mt][nf][2 * hh] * inv,
                                         oacc[mt][nf][2 * hh + 1] * inv);
                *(float2*)&o[(size_t)(qb * 128 + r) * HD + h * DHd + c] = val;
            }
        }
}

// ---------------- rmsnorm ----------------
__global__ __launch_bounds__(256) void rmsnorm_k(const float* __restrict__ in,
                                                 const float* __restrict__ w,
                                                 float* __restrict__ out, int cols) {
    int row = blockIdx.x;
    const float* r = in + (size_t)row * cols;
    float ss = 0.f;
    for (int i = threadIdx.x; i < cols; i += 256) { float v = r[i]; ss += v * v; }
    __shared__ float red[256];
    red[threadIdx.x] = ss; __syncthreads();
    for (int st = 128; st > 0; st >>= 1) {
        if (threadIdx.x < st) red[threadIdx.x] += red[threadIdx.x + st];
        __syncthreads();
    }
    float scale = rsqrtf(red[0] / (float)cols + EPSf);
    for (int i = threadIdx.x; i < cols; i += 256)
        out[(size_t)row * cols + i] = r[i] * scale * w[i];
}

// ---------------- RoPE ----------------
__global__ __launch_bounds__(256) void rope_k(float* __restrict__ q, int nheads) {
    int idx = blockIdx.x * 256 + threadIdx.x;
    int d = idx & 31;
    int h = (idx >> 5) % nheads;
    int s = idx / (32 * nheads);
    float inv = powf(1.0e6f, -(float)d / 32.f);
    float ang = (float)s * inv;
    float c = cosf(ang), sn = sinf(ang);
    float* base = q + (size_t)s * (nheads * DHd) + h * DHd;
    float x1 = base[d], x2 = base[d + 32];
    base[d]      = x1 * c - x2 * sn;
    base[d + 32] = x2 * c + x1 * sn;
}

// ---------------- router ----------------
__global__ __launch_bounds__(256) void reset_k() {
    if (threadIdx.x < En) g_cnt[threadIdx.x] = 0;
}

__global__ __launch_bounds__(256) void router_k(const float* __restrict__ Tm,
                                                const float* __restrict__ rw,
                                                const float* __restrict__ rb) {
    int row = blockIdx.x, tid = threadIdx.x;
    const float* r = Tm + (size_t)row * Dm;
    float loc[En] = {};
    for (int d = tid; d < Dm; d += 256) {
        float x = r[d];
#pragma unroll
        for (int e = 0; e < En; e++) loc[e] += x * rw[d * En + e];
    }
    __shared__ float sred[256 * En];
#pragma unroll
    for (int e = 0; e < En; e++) sred[tid * En + e] = loc[e];
    __syncthreads();
    for (int st = 128; st > 0; st >>= 1) {
        if (tid < st)
#pragma unroll
            for (int e = 0; e < En; e++) sred[tid * En + e] += sred[(tid + st) * En + e];
        __syncthreads();
    }
    if (tid == 0) {
        float sig[En], scv[En];
#pragma unroll
        for (int e = 0; e < En; e++) {
            float l = sred[e];
            sig[e] = 1.f / (1.f + expf(-l));
            scv[e] = sig[e] + rb[e];
        }
        int i0 = 0;
#pragma unroll
        for (int e = 1; e < En; e++) if (scv[e] > scv[i0]) i0 = e;
        int i1 = -1;
#pragma unroll
        for (int e = 0; e < En; e++)
            if (e != i0 && (i1 < 0 || scv[e] > scv[i1])) i1 = e;
        float a0 = sig[i0], a1 = sig[i1], s = a0 + a1;
        float w0 = a0 / s, w1 = a1 / s;
        int p = atomicAdd(&g_cnt[i0], 1);
        g_ptok[i0 * Sq + p] = row; g_pw[i0 * Sq + p] = w0; g_pslot[i0 * Sq + p] = 0;
        p = atomicAdd(&g_cnt[i1], 1);
        g_ptok[i1 * Sq + p] = row; g_pw[i1 * Sq + p] = w1; g_pslot[i1 * Sq + p] = 1;
    }
}

// ---------------- act = silu(gate)*up ----------------
__global__ __launch_bounds__(256) void act_k() {
    int e = blockIdx.z;
    int cnt = g_cnt[e];
    int i = blockIdx.x * 256 + threadIdx.x;
    int row = i >> 10;
    if (row >= cnt) return;
    size_t idx = (size_t)e * Sq * Id + i;
    float g = g_gate[idx];
    float u = g_up[idx];
    g_gate[idx] = (g / (1.f + expf(-g))) * u;
}

// ---------------- final: out = x1 + moe0 + moe1 ----------------
__global__ __launch_bounds__(256) void final_add_k(float* __restrict__ out) {
    int i = blockIdx.x * 256 + threadIdx.x;
    out[i] = out[i] + g_moe[i] + g_moe[(size_t)Sq * Dm + i];
}

// ---------------- host orchestration ----------------
extern "C" void kernel_launch(void* const* d_in, const int* in_sizes, int n_in,
                              void* d_out, int out_size) {
    const float* x    = (const float*)d_in[0];
    const float* ln1  = (const float*)d_in[1];
    const float* ln2  = (const float*)d_in[2];
    const float* wq   = (const float*)d_in[3];
    const float* wk   = (const float*)d_in[4];
    const float* wv   = (const float*)d_in[5];
    const float* wo   = (const float*)d_in[6];
    const float* qn   = (const float*)d_in[7];
    const float* kn   = (const float*)d_in[8];
    const float* rw   = (const float*)d_in[9];
    const float* rb   = (const float*)d_in[10];
    const float* wg   = (const float*)d_in[11];
    const float* wu   = (const float*)d_in[12];
    const float* wd   = (const float*)d_in[13];
    float* out = (float*)d_out;

    float *ph, *pq, *pk, *pv, *po, *pt, *pgate, *pup;
    cudaGetSymbolAddress((void**)&ph,    g_h);
    cudaGetSymbolAddress((void**)&pq,    g_q);
    cudaGetSymbolAddress((void**)&pk,    g_k);
    cudaGetSymbolAddress((void**)&pv,    g_v);
    cudaGetSymbolAddress((void**)&po,    g_o);
    cudaGetSymbolAddress((void**)&pt,    g_t);
    cudaGetSymbolAddress((void**)&pgate, g_gate);
    cudaGetSymbolAddress((void**)&pup,   g_up);

    cudaFuncSetAttribute(attn_mma, cudaFuncAttributeMaxDynamicSharedMemorySize, ATT_SMEM);

    // 1. h = rmsnorm(x, ln1)
    rmsnorm_k<<<Sq, 256>>>(x, ln1, ph, Dm);
    // 2. q,k,v projections (fp16 split mma)
    gemm_mma<false,false,false,false,true><<<dim3(HD/128,  Sq/128), 256, SMEM_SPLIT>>>(ph, wq, pq, nullptr, Sq, HD, Dm);
    gemm_mma<false,false,false,false,true><<<dim3(KVD/128, Sq/128), 256, SMEM_SPLIT>>>(ph, wk, pk, nullptr, Sq, KVD, Dm);
    gemm_mma<false,false,false,false,true><<<dim3(KVD/128, Sq/128), 256, SMEM_SPLIT>>>(ph, wv, pv, nullptr, Sq, KVD, Dm);
    // 3. q/k rmsnorm
    rmsnorm_k<<<Sq, 256>>>(pq, qn, pq, HD);
    rmsnorm_k<<<Sq, 256>>>(pk, kn, pk, KVD);
    // 4. RoPE
    rope_k<<<(Sq * Hn * 32) / 256, 256>>>(pq, Hn);
    rope_k<<<(Sq * KVn * 32) / 256, 256>>>(pk, KVn);
    // 5. attention (fp16 split mma flash)
    attn_mma<<<dim3(Sq / 128, Hn), 256, ATT_SMEM>>>(pq, pk, pv, po);
    // 6. x1 = x + o @ wo (fp16 split mma)
    gemm_mma<false,false,false,true,true><<<dim3(Dm/128, Sq/128), 256, SMEM_SPLIT>>>(po, wo, out, x, Sq, Dm, HD);
    // 7. t = rmsnorm(x1, ln2)
    rmsnorm_k<<<Sq, 256>>>(out, ln2, pt, Dm);
    // 8. routing
    reset_k<<<1, 256>>>();
    router_k<<<Sq, 256>>>(pt, rw, rb);
    // 9. expert gate/up (gathered, single fp16 mma)
    gemm_mma<true,false,true,false,false><<<dim3(Id/128, Sq/128, En), 256, SMEM_SINGLE>>>(pt, wg, pgate, nullptr, Sq, Id, Dm);
    gemm_mma<true,false,true,false,false><<<dim3(Id/128, Sq/128, En), 256, SMEM_SINGLE>>>(pt, wu, pup, nullptr, Sq, Id, Dm);
    // 10. act
    act_k<<<dim3((Sq * Id) / 256, 1, En), 256>>>();
    // 11. down GEMM + weighted scatter (single fp16 mma)
    gemm_mma<false,true,true,false,false><<<dim3(Dm/128, Sq/128, En), 256, SMEM_SINGLE>>>(pgate, wd, nullptr, nullptr, Sq, Dm, Id);
    // 12. out = x1 + moe
    final_add_k<<<(Sq * Dm) / 256, 256>>>(out);
}

// round 6
// speedup vs baseline: 4.3039x; 1.0728x over previous
#include <cuda_runtime.h>
#include <cuda_fp16.h>
#include <math.h>
#include <stdint.h>

// ---------------- problem constants ----------------
#define Sq   2048
#define Dm   2048
#define Hn   16
#define KVn  4
#define DHd  128
#define En   8
#define Id   1024
#define HD   2048
#define KVD  512
#define EPSf 1e-6f

// ---------------- static device scratch ----------------
__device__ float g_q   [Sq*HD];
__device__ float g_k   [Sq*KVD];
__device__ float g_v   [Sq*KVD];
__device__ float g_t   [Sq*Dm];
__device__ float g_gate[En*Sq*Id];
__device__ float g_up  [En*Sq*Id];
__device__ float g_moe [2*Sq*Dm];
__device__ int   g_cnt [En];
__device__ int   g_ptok[En*Sq];
__device__ float g_pw  [En*Sq];
__device__ int   g_pslot[En*Sq];
// fp16 activations
__device__ __half g_hh [Sq*Dm];
__device__ __half g_hl [Sq*Dm];
__device__ __half g_qh [Sq*HD];
__device__ __half g_ql [Sq*HD];
__device__ __half g_kh2[Sq*KVD];
__device__ __half g_kl2[Sq*KVD];
__device__ __half g_vh [Sq*KVD];
__device__ __half g_vl [Sq*KVD];
__device__ __half g_oh [Sq*HD];
__device__ __half g_ol [Sq*HD];
__device__ __half g_th [Sq*Dm];
__device__ __half g_acth[En*Sq*Id];
// fp16 weights
__device__ __half w_qh[Dm*HD];
__device__ __half w_ql[Dm*HD];
__device__ __half w_kh[Dm*KVD];
__device__ __half w_kl[Dm*KVD];
__device__ __half w_vh[Dm*KVD];
__device__ __half w_vl[Dm*KVD];
__device__ __half w_oh[HD*Dm];
__device__ __half w_ol[HD*Dm];
__device__ __half w_gh[En*Dm*Id];
__device__ __half w_uh[En*Dm*Id];
__device__ __half w_dh[En*Id*Dm];

// ---------------- helpers ----------------
__device__ __forceinline__ uint32_t smem_u32(const void* p) {
    uint32_t a;
    asm("{ .reg .u64 t; cvta.to.shared.u64 t, %1; cvt.u32.u64 %0, t; }" : "=r"(a) : "l"(p));
    return a;
}
__device__ __forceinline__ void ldsm4(uint32_t* r, uint32_t a) {
    asm volatile("ldmatrix.sync.aligned.m8n8.x4.shared.b16 {%0,%1,%2,%3}, [%4];"
                 : "=r"(r[0]), "=r"(r[1]), "=r"(r[2]), "=r"(r[3]) : "r"(a));
}
__device__ __forceinline__ void ldsm4t(uint32_t* r, uint32_t a) {
    asm volatile("ldmatrix.sync.aligned.m8n8.x4.trans.shared.b16 {%0,%1,%2,%3}, [%4];"
                 : "=r"(r[0]), "=r"(r[1]), "=r"(r[2]), "=r"(r[3]) : "r"(a));
}
__device__ __forceinline__ void mma16816(float* d, const uint32_t* a, const uint32_t* b) {
    asm volatile("mma.sync.aligned.m16n8k16.row.col.f32.f16.f16.f32 "
                 "{%0,%1,%2,%3}, {%4,%5,%6,%7}, {%8,%9}, {%0,%1,%2,%3};"
                 : "+f"(d[0]), "+f"(d[1]), "+f"(d[2]), "+f"(d[3])
                 : "r"(a[0]), "r"(a[1]), "r"(a[2]), "r"(a[3]), "r"(b[0]), "r"(b[1]));
}
__device__ __forceinline__ void split2(float x, float y, half2& hi, half2& lo) {
    hi = __floats2half2_rn(x, y);
    lo = __floats2half2_rn(x - __low2float(hi), y - __high2float(hi));
}
#define CP16(dst, src) \
    asm volatile("cp.async.cg.shared.global [%0], [%1], 16;" :: "r"((uint32_t)(dst)), "l"(src))
#define CP_COMMIT() asm volatile("cp.async.commit_group;" ::: "memory")
#define CP_WAIT(n)  asm volatile("cp.async.wait_group %0;" :: "n"(n) : "memory")

// ---------------- weight/activation converts ----------------
__global__ __launch_bounds__(256) void conv_split_k(const float* __restrict__ s,
                                                    __half* __restrict__ hi,
                                                    __half* __restrict__ lo) {
    size_t i = ((size_t)blockIdx.x * 256 + threadIdx.x) * 4;
    float4 v = *(const float4*)(s + i);
    half2 h0, l0, h1, l1;
    split2(v.x, v.y, h0, l0); split2(v.z, v.w, h1, l1);
    *(half2*)(hi + i) = h0; *(half2*)(hi + i + 2) = h1;
    *(half2*)(lo + i) = l0; *(half2*)(lo + i + 2) = l1;
}
__global__ __launch_bounds__(256) void conv_single_k(const float* __restrict__ s,
                                                     __half* __restrict__ hi) {
    size_t i = ((size_t)blockIdx.x * 256 + threadIdx.x) * 4;
    float4 v = *(const float4*)(s + i);
    *(half2*)(hi + i)     = __floats2half2_rn(v.x, v.y);
    *(half2*)(hi + i + 2) = __floats2half2_rn(v.z, v.w);
}

// ================= fp16 mma GEMM, cp.async double-buffered =================
#define AT_SZ 10240     // 128 rows x 80B
#define BT_SZ 8704      // 32 rows x 272B
#define SM_SPLIT  (2048 + 2*(2*AT_SZ + 2*BT_SZ))   // 77824
#define SM_SINGLE (2048 + 2*(AT_SZ + BT_SZ))       // 39936

template<bool GATHER, bool SCATTER, bool EXPERT, bool RES, bool SPLIT>
__global__ __launch_bounds__(256, 2) void gemm_mma2(
    const __half* __restrict__ Ah, const __half* __restrict__ Al,
    const __half* __restrict__ Bh, const __half* __restrict__ Bl,
    float* __restrict__ C, const float* __restrict__ res,
    int M, int N, int K)
{
    extern __shared__ char smem[];
    const int tid = threadIdx.x, lane = tid & 31, wid = tid >> 5;
    const int wm = wid & 3, wn = wid >> 2;
    const int STG  = SPLIT ? (2 * AT_SZ + 2 * BT_SZ) : (AT_SZ + BT_SZ);
    const int BOFF = SPLIT ? 2 * AT_SZ : AT_SZ;

    int e = 0, cnt = M;
    const __half* Ahe = Ah;
    const __half* Bhe = Bh;
    const __half* Ble = Bl;
    float* Ce = C;
    if (EXPERT) {
        e = blockIdx.z;
        cnt = g_cnt[e];
        Bhe = Bh + (size_t)e * K * N;
        if (SPLIT) Ble = Bl + (size_t)e * K * N;
        if (!GATHER) Ahe = Ah + (size_t)e * Sq * K;
        if (!SCATTER) Ce = C + (size_t)e * Sq * N;
    }
    const int m0 = blockIdx.y * 128;
    if (EXPERT && m0 >= cnt) return;
    const int n0 = blockIdx.x * 128;

    int*   stok = (int*)smem;
    float* swt  = (float*)(smem + 512);
    int*   ssl  = (int*)(smem + 1024);
    if (GATHER || SCATTER) {
        if (tid < 128) {
            int r = m0 + tid;
            bool ok = r < cnt;
            stok[tid] = ok ? g_ptok[e * Sq + r] : 0;
            if (SCATTER) {
                swt[tid] = ok ? g_pw[e * Sq + r] : 0.f;
                ssl[tid] = ok ? g_pslot[e * Sq + r] : 0;
            }
        }
        __syncthreads();
    }
    const uint32_t sb = smem_u32(smem);
    const uint32_t tb = sb + 2048;
    const int T = K / 32;

#define ISSUE(it) do { \
        int _k0 = (it) * 32; \
        uint32_t _s0 = tb + ((it) & 1) * STG; \
        _Pragma("unroll") \
        for (int _j = 0; _j < 2; _j++) { \
            int _idx = tid + _j * 256; \
            int _row = _idx >> 2, _c = _idx & 3; \
            int _gr = GATHER ? stok[_row] : (m0 + _row); \
            CP16(_s0 + _row * 80 + _c * 16, Ahe + (size_t)_gr * K + _k0 + _c * 8); \
            if (SPLIT) CP16(_s0 + AT_SZ + _row * 80 + _c * 16, Al + (size_t)_gr * K + _k0 + _c * 8); \
        } \
        _Pragma("unroll") \
        for (int _j = 0; _j < 2; _j++) { \
            int _idx = tid + _j * 256; \
            int _row = _idx >> 4, _c = _idx & 15; \
            CP16(_s0 + BOFF + _row * 272 + _c * 16, Bhe + (size_t)(_k0 + _row) * N + n0 + _c * 8); \
            if (SPLIT) CP16(_s0 + BOFF + BT_SZ + _row * 272 + _c * 16, \
                            Ble + (size_t)(_k0 + _row) * N + n0 + _c * 8); \
        } \
        CP_COMMIT(); \
    } while (0)

    ISSUE(0);
    float acc[2][8][4] = {};
    for (int it = 0; it < T; ++it) {
        if (it + 1 < T) { ISSUE(it + 1); CP_WAIT(1); }
        else            { CP_WAIT(0); }
        __syncthreads();
        uint32_t s0 = tb + (it & 1) * STG;
#pragma unroll
        for (int ks = 0; ks < 2; ks++) {
            uint32_t ah[2][4], al[2][4], bh[8][2], bl[8][2];
            int am = wm * 32 + (lane & 7) + ((lane >> 3) & 1) * 8;
            int ak = ks * 16 + (lane >> 4) * 8;
            uint32_t ab = s0 + am * 80 + ak * 2;
            ldsm4(ah[0], ab);
            ldsm4(ah[1], ab + 16 * 80);
            if (SPLIT) { ldsm4(al[0], ab + AT_SZ); ldsm4(al[1], ab + AT_SZ + 16 * 80); }
            int bk = ks * 16 + (lane & 7) + ((lane >> 3) & 1) * 8;
            int bn = wn * 64 + (lane >> 4) * 8;
            uint32_t bb = s0 + BOFF + bk * 272 + bn * 2;
#pragma unroll
            for (int t = 0; t < 4; t++) {
                uint32_t rr[4];
                ldsm4t(rr, bb + t * 32);
                bh[2 * t][0] = rr[0]; bh[2 * t][1] = rr[1];
                bh[2 * t + 1][0] = rr[2]; bh[2 * t + 1][1] = rr[3];
                if (SPLIT) {
                    ldsm4t(rr, bb + BT_SZ + t * 32);
                    bl[2 * t][0] = rr[0]; bl[2 * t][1] = rr[1];
                    bl[2 * t + 1][0] = rr[2]; bl[2 * t + 1][1] = rr[3];
                }
            }
#pragma unroll
            for (int mt = 0; mt < 2; mt++)
#pragma unroll
                for (int nt = 0; nt < 8; nt++) {
                    mma16816(acc[mt][nt], ah[mt], bh[nt]);
                    if (SPLIT) {
                        mma16816(acc[mt][nt], ah[mt], bl[nt]);
                        mma16816(acc[mt][nt], al[mt], bh[nt]);
                    }
                }
        }
        __syncthreads();
    }
#undef ISSUE

    const int g = lane >> 2, tig = lane & 3;
#pragma unroll
    for (int mt = 0; mt < 2; mt++) {
#pragma unroll
        for (int hh = 0; hh < 2; hh++) {
            int row = wm * 32 + mt * 16 + g + hh * 8;
            if (EXPERT && m0 + row >= cnt) continue;
            if (SCATTER) {
                int token = stok[row]; float w = swt[row]; int slot = ssl[row];
                float* dst = g_moe + ((size_t)slot * Sq + token) * Dm + n0;
#pragma unroll
                for (int nt = 0; nt < 8; nt++) {
                    int c = wn * 64 + nt * 8 + tig * 2;
                    *(float2*)(dst + c) =
                        make_float2(w * acc[mt][nt][2 * hh], w * acc[mt][nt][2 * hh + 1]);
                }
            } else {
                float* dst = Ce + (size_t)(m0 + row) * N + n0;
                const float* rs = RES ? (res + (size_t)(m0 + row) * N + n0) : nullptr;
#pragma unroll
                for (int nt = 0; nt < 8; nt++) {
                    int c = wn * 64 + nt * 8 + tig * 2;
                    float2 v = make_float2(acc[mt][nt][2 * hh], acc[mt][nt][2 * hh + 1]);
                    if (RES) { v.x += rs[c]; v.y += rs[c + 1]; }
                    *(float2*)(dst + c) = v;
                }
            }
        }
    }
}

// ================= tensor-core flash attention (fp16 split, causal, GQA) =================
#define QH_O 0
#define QL_O 34816
#define KH_O 69632
#define KL_O 87040
#define VH_O 104448
#define VL_O 121856
#define PH_O 139264
#define PL_O 157696
#define MAXB_O 176128
#define SUMB_O 177152
#define MROW_O 178176
#define LROW_O 178688
#define ATT_SMEM 179200
#define LDP 72

__global__ __launch_bounds__(256) void attn_mma(float* __restrict__ dummy) {
    extern __shared__ char smem[];
    const uint32_t sb = smem_u32(smem);
    const int qb = gridDim.x - 1 - blockIdx.x;
    const int h = blockIdx.y, kvh = h >> 2;
    const int tid = threadIdx.x, lane = tid & 31, wid = tid >> 5;
    const int wm = wid & 3, wn = wid >> 2;
    float* Mrow = (float*)(smem + MROW_O);
    float* Lrow = (float*)(smem + LROW_O);
    float* maxb = (float*)(smem + MAXB_O);
    float* sumb = (float*)(smem + SUMB_O);

    // ---- stage Q hi/lo (pre-scaled in qk_fin_k) via cp.async ----
#pragma unroll
    for (int j = 0; j < 16; j++) {
        int idx = tid + j * 256;
        int arr = j >> 3;                    // 0=hi 1=lo
        int r = (idx & 2047) >> 4, c = idx & 15;
        const __half* src = (arr ? g_ql : g_qh) + (size_t)(qb * 128 + r) * HD + h * DHd + c * 8;
        CP16(sb + (arr ? QL_O : QH_O) + r * 272 + c * 16, src);
    }
    CP_COMMIT();
    if (tid < 128) { Mrow[tid] = -INFINITY; Lrow[tid] = 0.f; }

    float oacc[2][8][4] = {};
    const int g = lane >> 2, tig = lane & 3;
    const int arow = wm * 32 + (lane & 7) + ((lane >> 3) & 1) * 8;
    const int brow = wn * 32 + (lane & 7) + 8 * (lane >> 4);

    for (int kbg = 0; kbg <= 2 * qb + 1; kbg++) {
        __syncthreads();   // prev PV-MMA done with V smem / P reuse
        // ---- stage K,V hi/lo via cp.async ----
#pragma unroll
        for (int j = 0; j < 16; j++) {
            int idx = tid + j * 256;
            int arr = j >> 2;                // 0=khi 1=klo 2=vhi 3=vlo
            int r = (idx & 1023) >> 4, c = idx & 15;
            const __half* src;
            uint32_t doff;
            if (arr == 0)      { src = g_kh2; doff = KH_O; }
            else if (arr == 1) { src = g_kl2; doff = KL_O; }
            else if (arr == 2) { src = g_vh;  doff = VH_O; }
            else               { src = g_vl;  doff = VL_O; }
            CP16(sb + doff + r * 272 + c * 16,
                 src + (size_t)(kbg * 64 + r) * KVD + kvh * DHd + c * 8);
        }
        CP_COMMIT();
        CP_WAIT(0);
        __syncthreads();

        // ---- S = Q @ K^T (split) ----
        float sacc[2][4][4] = {};
#pragma unroll
        for (int ks = 0; ks < 8; ks++) {
            uint32_t ah[2][4], al[2][4], bh[4][2], bl[4][2];
            int ak = ks * 16 + (lane >> 4) * 8;
            uint32_t ab = sb + QH_O + (arow * 136 + ak) * 2;
            ldsm4(ah[0], ab);
            ldsm4(ah[1], ab + 16 * 272);
            ldsm4(al[0], ab + (QL_O - QH_O));
            ldsm4(al[1], ab + (QL_O - QH_O) + 16 * 272);
            int bk = ks * 16 + ((lane >> 3) & 1) * 8;
#pragma unroll
            for (int t = 0; t < 2; t++) {
                uint32_t rr[4];
                uint32_t bb = sb + KH_O + ((brow + t * 16) * 136 + bk) * 2;
                ldsm4(rr, bb);
                bh[2 * t][0] = rr[0]; bh[2 * t][1] = rr[1];
                bh[2 * t + 1][0] = rr[2]; bh[2 * t + 1][1] = rr[3];
                ldsm4(rr, bb + (KL_O - KH_O));
                bl[2 * t][0] = rr[0]; bl[2 * t][1] = rr[1];
                bl[2 * t + 1][0] = rr[2]; bl[2 * t + 1][1] = rr[3];
            }
#pragma unroll
            for (int mt = 0; mt < 2; mt++)
#pragma unroll
                for (int nf = 0; nf < 4; nf++) {
                    mma16816(sacc[mt][nf], ah[mt], bh[nf]);
                    mma16816(sacc[mt][nf], ah[mt], bl[nf]);
                    mma16816(sacc[mt][nf], al[mt], bh[nf]);
                }
        }

        if (kbg >= 2 * qb) {
#pragma unroll
            for (int mt = 0; mt < 2; mt++)
#pragma unroll
                for (int nf = 0; nf < 4; nf++)
#pragma unroll
                    for (int i = 0; i < 4; i++) {
                        int row = qb * 128 + wm * 32 + mt * 16 + g + (i >= 2 ? 8 : 0);
                        int col = kbg * 64 + wn * 32 + nf * 8 + tig * 2 + (i & 1);
                        if (col > row) sacc[mt][nf][i] = -INFINITY;
                    }
        }

        float rmax[2][2];
#pragma unroll
        for (int mt = 0; mt < 2; mt++)
#pragma unroll
            for (int hh = 0; hh < 2; hh++) {
                float m = -INFINITY;
#pragma unroll
                for (int nf = 0; nf < 4; nf++)
                    m = fmaxf(m, fmaxf(sacc[mt][nf][2 * hh], sacc[mt][nf][2 * hh + 1]));
                m = fmaxf(m, __shfl_xor_sync(0xffffffffu, m, 1));
                m = fmaxf(m, __shfl_xor_sync(0xffffffffu, m, 2));
                rmax[mt][hh] = m;
            }
        if (tig == 0) {
#pragma unroll
            for (int mt = 0; mt < 2; mt++) {
                int r = wm * 32 + mt * 16 + g;
                maxb[wn * 128 + r] = rmax[mt][0];
                maxb[wn * 128 + r + 8] = rmax[mt][1];
            }
        }
        __syncthreads();

        float alpha[2][2], mnew[2][2], rsum[2][2];
#pragma unroll
        for (int mt = 0; mt < 2; mt++)
#pragma unroll
            for (int hh = 0; hh < 2; hh++) {
                int r = wm * 32 + mt * 16 + g + hh * 8;
                float mo = Mrow[r];
                float mn = fmaxf(mo, fmaxf(maxb[r], maxb[128 + r]));
                mnew[mt][hh] = mn;
                alpha[mt][hh] = expf(mo - mn);
                rsum[mt][hh] = 0.f;
            }
#pragma unroll
        for (int mt = 0; mt < 2; mt++)
#pragma unroll
            for (int nf = 0; nf < 4; nf++) {
#pragma unroll
                for (int hh = 0; hh < 2; hh++) {
                    float p0 = expf(sacc[mt][nf][2 * hh]     - mnew[mt][hh]);
                    float p1 = expf(sacc[mt][nf][2 * hh + 1] - mnew[mt][hh]);
                    rsum[mt][hh] += p0 + p1;
                    half2 hi, lo;
                    split2(p0, p1, hi, lo);
                    int r = wm * 32 + mt * 16 + g + hh * 8;
                    int c = wn * 32 + nf * 8 + tig * 2;
                    *(half2*)(smem + PH_O + (r * LDP + c) * 2) = hi;
                    *(half2*)(smem + PL_O + (r * LDP + c) * 2) = lo;
                }
            }
#pragma unroll
        for (int mt = 0; mt < 2; mt++)
#pragma unroll
            for (int hh = 0; hh < 2; hh++) {
                float s = rsum[mt][hh];
                s += __shfl_xor_sync(0xffffffffu, s, 1);
                s += __shfl_xor_sync(0xffffffffu, s, 2);
                rsum[mt][hh] = s;
            }
        if (tig == 0) {
#pragma unroll
            for (int mt = 0; mt < 2; mt++) {
                int r = wm * 32 + mt * 16 + g;
                sumb[wn * 128 + r] = rsum[mt][0];
                sumb[wn * 128 + r + 8] = rsum[mt][1];
            }
        }
#pragma unroll
        for (int mt = 0; mt < 2; mt++)
#pragma unroll
            for (int nf = 0; nf < 8; nf++) {
                oacc[mt][nf][0] *= alpha[mt][0]; oacc[mt][nf][1] *= alpha[mt][0];
                oacc[mt][nf][2] *= alpha[mt][1]; oacc[mt][nf][3] *= alpha[mt][1];
            }
        __syncthreads();

        if (wn == 0 && tig == 0) {
#pragma unroll
            for (int mt = 0; mt < 2; mt++)
#pragma unroll
                for (int hh = 0; hh < 2; hh++) {
                    int r = wm * 32 + mt * 16 + g + hh * 8;
                    Lrow[r] = Lrow[r] * alpha[mt][hh] + sumb[r] + sumb[128 + r];
                    Mrow[r] = mnew[mt][hh];
                }
        }

        // ---- O += P @ V (split) ----
#pragma unroll
        for (int ks = 0; ks < 4; ks++) {
            uint32_t ph[2][4], pl[2][4], vh[8][2], vl[8][2];
            int ak = ks * 16 + (lane >> 4) * 8;
            uint32_t ab = sb + PH_O + (arow * LDP + ak) * 2;
            ldsm4(ph[0], ab);
            ldsm4(ph[1], ab + 16 * LDP * 2);
            ldsm4(pl[0], ab + (PL_O - PH_O));
            ldsm4(pl[1], ab + (PL_O - PH_O) + 16 * LDP * 2);
            int vk = ks * 16 + (lane & 7) + ((lane >> 3) & 1) * 8;
            int vn = wn * 64 + (lane >> 4) * 8;
            uint32_t vb = sb + VH_O + (vk * 136 + vn) * 2;
#pragma unroll
            for (int ntp = 0; ntp < 4; ntp++) {
                uint32_t rr[4];
                ldsm4t(rr, vb + ntp * 32);
                vh[2 * ntp][0] = rr[0]; vh[2 * ntp][1] = rr[1];
                vh[2 * ntp + 1][0] = rr[2]; vh[2 * ntp + 1][1] = rr[3];
                ldsm4t(rr, vb + (VL_O - VH_O) + ntp * 32);
                vl[2 * ntp][0] = rr[0]; vl[2 * ntp][1] = rr[1];
                vl[2 * ntp + 1][0] = rr[2]; vl[2 * ntp + 1][1] = rr[3];
            }
#pragma unroll
            for (int mt = 0; mt < 2; mt++)
#pragma unroll
                for (int nf = 0; nf < 8; nf++) {
                    mma16816(oacc[mt][nf], ph[mt], vh[nf]);
                    mma16816(oacc[mt][nf], ph[mt], vl[nf]);
                    mma16816(oacc[mt][nf], pl[mt], vh[nf]);
                }
        }
    }

    __syncthreads();
#pragma unroll
    for (int mt = 0; mt < 2; mt++)
#pragma unroll
        for (int hh = 0; hh < 2; hh++) {
            int r = wm * 32 + mt * 16 + g + hh * 8;
            float inv = 1.f / Lrow[r];
#pragma unroll
            for (int nf = 0; nf < 8; nf++) {
                int c = wn * 64 + nf * 8 + tig * 2;
                float vx = oacc[mt][nf][2 * hh] * inv;
                float vy = oacc[mt][nf][2 * hh + 1] * inv;
                half2 hi, lo;
                split2(vx, vy, hi, lo);
                size_t dst = (size_t)(qb * 128 + r) * HD + h * DHd + c;
                *(half2*)&g_oh[dst] = hi;
                *(half2*)&g_ol[dst] = lo;
            }
        }
}

// ---------------- rmsnorm variants ----------------
__global__ __launch_bounds__(256) void rmsnorm_k(const float* __restrict__ in,
                                                 const float* __restrict__ w,
                                                 float* __restrict__ out, int cols) {
    int row = blockIdx.x;
    const float* r = in + (size_t)row * cols;
    float ss = 0.f;
    for (int i = threadIdx.x; i < cols; i += 256) { float v = r[i]; ss += v * v; }
    __shared__ float red[256];
    red[threadIdx.x] = ss; __syncthreads();
    for (int st = 128; st > 0; st >>= 1) {
        if (threadIdx.x < st) red[threadIdx.x] += red[threadIdx.x + st];
        __syncthreads();
    }
    float scale = rsqrtf(red[0] / (float)cols + EPSf);
    for (int i = threadIdx.x; i < cols; i += 256)
        out[(size_t)row * cols + i] = r[i] * scale * w[i];
}

__global__ __launch_bounds__(256) void rmsnorm_hl_k(const float* __restrict__ in,
                                                    const float* __restrict__ w,
                                                    __half* __restrict__ ohi,
                                                    __half* __restrict__ olo, int cols) {
    int row = blockIdx.x;
    const float* r = in + (size_t)row * cols;
    float ss = 0.f;
    for (int i = threadIdx.x; i < cols; i += 256) { float v = r[i]; ss += v * v; }
    __shared__ float red[256];
    red[threadIdx.x] = ss; __syncthreads();
    for (int st = 128; st > 0; st >>= 1) {
        if (threadIdx.x < st) red[threadIdx.x] += red[threadIdx.x + st];
        __syncthreads();
    }
    float scale = rsqrtf(red[0] / (float)cols + EPSf);
    for (int i = threadIdx.x; i < cols; i += 256) {
        float val = r[i] * scale * w[i];
        __half hv = __float2half_rn(val);
        ohi[(size_t)row * cols + i] = hv;
        olo[(size_t)row * cols + i] = __float2half_rn(val - __half2float(hv));
    }
}

__global__ __launch_bounds__(256) void rmsnorm_th_k(const float* __restrict__ in,
                                                    const float* __restrict__ w,
                                                    float* __restrict__ out,
                                                    __half* __restrict__ ohi, int cols) {
    int row = blockIdx.x;
    const float* r = in + (size_t)row * cols;
    float ss = 0.f;
    for (int i = threadIdx.x; i < cols; i += 256) { float v = r[i]; ss += v * v; }
    __shared__ float red[256];
    red[threadIdx.x] = ss; __syncthreads();
    for (int st = 128; st > 0; st >>= 1) {
        if (threadIdx.x < st) red[threadIdx.x] += red[threadIdx.x + st];
        __syncthreads();
    }
    float scale = rsqrtf(red[0] / (float)cols + EPSf);
    for (int i = threadIdx.x; i < cols; i += 256) {
        float val = r[i] * scale * w[i];
        out[(size_t)row * cols + i] = val;
        ohi[(size_t)row * cols + i] = __float2half_rn(val);
    }
}

// ---------------- RoPE + hi/lo emit (q scaled) ----------------
__global__ __launch_bounds__(256) void qk_fin_k(const float* __restrict__ src,
                                                __half* __restrict__ hi,
                                                __half* __restrict__ lo,
                                                int nheads, float scale) {
    int idx = blockIdx.x * 256 + threadIdx.x;      // Sq*nheads*128
    int d = idx & 127;
    int rest = idx >> 7;
    int h = rest % nheads;
    int s = rest / nheads;
    const float* base = src + (size_t)s * (nheads * DHd) + h * DHd;
    float val;
    if (d < 32) {
        float inv = powf(1.0e6f, -(float)d / 32.f);
        float a = (float)s * inv;
        val = base[d] * cosf(a) - base[d + 32] * sinf(a);
    } else if (d < 64) {
        int p = d - 32;
        float inv = powf(1.0e6f, -(float)p / 32.f);
        float a = (float)s * inv;
        val = base[d] * cosf(a) + base[d - 32] * sinf(a);
    } else {
        val = base[d];
    }
    val *= scale;
    __half hv = __float2half_rn(val);
    hi[idx] = hv;
    lo[idx] = __float2half_rn(val - __half2float(hv));
}

// ---------------- router ----------------
__global__ __launch_bounds__(256) void reset_k() {
    if (threadIdx.x < En) g_cnt[threadIdx.x] = 0;
}

__global__ __launch_bounds__(256) void router_k(const float* __restrict__ Tm,
                                                const float* __restrict__ rw,
                                                const float* __restrict__ rb) {
    int row = blockIdx.x, tid = threadIdx.x;
    const float* r = Tm + (size_t)row * Dm;
    float loc[En] = {};
    for (int d = tid; d < Dm; d += 256) {
        float x = r[d];
#pragma unroll
        for (int e = 0; e < En; e++) loc[e] += x * rw[d * En + e];
    }
    __shared__ float sred[256 * En];
#pragma unroll
    for (int e = 0; e < En; e++) sred[tid * En + e] = loc[e];
    __syncthreads();
    for (int st = 128; st > 0; st >>= 1) {
        if (tid < st)
#pragma unroll
            for (int e = 0; e < En; e++) sred[tid * En + e] += sred[(tid + st) * En + e];
        __syncthreads();
    }
    if (tid == 0) {
        float sig[En], scv[En];
#pragma unroll
        for (int e = 0; e < En; e++) {
            float l = sred[e];
            sig[e] = 1.f / (1.f + expf(-l));
            scv[e] = sig[e] + rb[e];
        }
        int i0 = 0;
#pragma unroll
        for (int e = 1; e < En; e++) if (scv[e] > scv[i0]) i0 = e;
        int i1 = -1;
#pragma unroll
        for (int e = 0; e < En; e++)
            if (e != i0 && (i1 < 0 || scv[e] > scv[i1])) i1 = e;
        float a0 = sig[i0], a1 = sig[i1], s = a0 + a1;
        float w0 = a0 / s, w1 = a1 / s;
        int p = atomicAdd(&g_cnt[i0], 1);
        g_ptok[i0 * Sq + p] = row; g_pw[i0 * Sq + p] = w0; g_pslot[i0 * Sq + p] = 0;
        p = atomicAdd(&g_cnt[i1], 1);
        g_ptok[i1 * Sq + p] = row; g_pw[i1 * Sq + p] = w1; g_pslot[i1 * Sq + p] = 1;
    }
}

// ---------------- act = silu(gate)*up -> half ----------------
__global__ __launch_bounds__(256) void act_k() {
    int e = blockIdx.z;
    int cnt = g_cnt[e];
    int i = blockIdx.x * 256 + threadIdx.x;
    int row = i >> 10;
    if (row >= cnt) return;
    size_t idx = (size_t)e * Sq * Id + i;
    float g = g_gate[idx];
    float u = g_up[idx];
    g_acth[idx] = __float2half_rn((g / (1.f + expf(-g))) * u);
}

// ---------------- final: out = x1 + moe0 + moe1 ----------------
__global__ __launch_bounds__(256) void final_add_k(float* __restrict__ out) {
    int i = blockIdx.x * 256 + threadIdx.x;
    out[i] = out[i] + g_moe[i] + g_moe[(size_t)Sq * Dm + i];
}

// ---------------- host orchestration ----------------
extern "C" void kernel_launch(void* const* d_in, const int* in_sizes, int n_in,
                              void* d_out, int out_size) {
    const float* x    = (const float*)d_in[0];
    const float* ln1  = (const float*)d_in[1];
    const float* ln2  = (const float*)d_in[2];
    const float* wq   = (const float*)d_in[3];
    const float* wk   = (const float*)d_in[4];
    const float* wv   = (const float*)d_in[5];
    const float* wo   = (const float*)d_in[6];
    const float* rw   = (const float*)d_in[9];
    const float* rb   = (const float*)d_in[10];
    const float* wg   = (const float*)d_in[11];
    const float* wu   = (const float*)d_in[12];
    const float* wd   = (const float*)d_in[13];
    const float* qn   = (const float*)d_in[7];
    const float* kn   = (const float*)d_in[8];
    float* out = (float*)d_out;

    float *pq, *pk, *pv, *pt, *pgate, *pup;
    cudaGetSymbolAddress((void**)&pq,    g_q);
    cudaGetSymbolAddress((void**)&pk,    g_k);
    cudaGetSymbolAddress((void**)&pv,    g_v);
    cudaGetSymbolAddress((void**)&pt,    g_t);
    cudaGetSymbolAddress((void**)&pgate, g_gate);
    cudaGetSymbolAddress((void**)&pup,   g_up);
    __half *hh, *hl, *qh, *ql, *kh, *kl, *vh, *vl, *oh, *ol, *th, *acth;
    cudaGetSymbolAddress((void**)&hh, g_hh);   cudaGetSymbolAddress((void**)&hl, g_hl);
    cudaGetSymbolAddress((void**)&qh, g_qh);   cudaGetSymbolAddress((void**)&ql, g_ql);
    cudaGetSymbolAddress((void**)&kh, g_kh2);  cudaGetSymbolAddress((void**)&kl, g_kl2);
    cudaGetSymbolAddress((void**)&vh, g_vh);   cudaGetSymbolAddress((void**)&vl, g_vl);
    cudaGetSymbolAddress((void**)&oh, g_oh);   cudaGetSymbolAddress((void**)&ol, g_ol);
    cudaGetSymbolAddress((void**)&th, g_th);   cudaGetSymbolAddress((void**)&acth, g_acth);
    __half *wqh, *wql, *wkh, *wkl, *wvh, *wvl, *woh, *wol, *wgh, *wuh, *wdh;
    cudaGetSymbolAddress((void**)&wqh, w_qh); cudaGetSymbolAddress((void**)&wql, w_ql);
    cudaGetSymbolAddress((void**)&wkh, w_kh); cudaGetSymbolAddress((void**)&wkl, w_kl);
    cudaGetSymbolAddress((void**)&wvh, w_vh); cudaGetSymbolAddress((void**)&wvl, w_vl);
    cudaGetSymbolAddress((void**)&woh, w_oh); cudaGetSymbolAddress((void**)&wol, w_ol);
    cudaGetSymbolAddress((void**)&wgh, w_gh); cudaGetSymbolAddress((void**)&wuh, w_uh);
    cudaGetSymbolAddress((void**)&wdh, w_dh);

    cudaFuncSetAttribute(attn_mma, cudaFuncAttributeMaxDynamicSharedMemorySize, ATT_SMEM);
    cudaFuncSetAttribute(gemm_mma2<false,false,false,false,true>, cudaFuncAttributeMaxDynamicSharedMemorySize, SM_SPLIT);
    cudaFuncSetAttribute(gemm_mma2<false,false,false,true ,true>, cudaFuncAttributeMaxDynamicSharedMemorySize, SM_SPLIT);
    cudaFuncSetAttribute(gemm_mma2<true ,false,true ,false,false>, cudaFuncAttributeMaxDynamicSharedMemorySize, SM_SINGLE);
    cudaFuncSetAttribute(gemm_mma2<false,true ,true ,false,false>, cudaFuncAttributeMaxDynamicSharedMemorySize, SM_SINGLE);

    // 0. weight conversions (per replay; memory-bound ~70us)
    conv_split_k <<<Dm*HD /1024, 256>>>(wq, wqh, wql);
    conv_split_k <<<Dm*KVD/1024, 256>>>(wk, wkh, wkl);
    conv_split_k <<<Dm*KVD/1024, 256>>>(wv, wvh, wvl);
    conv_split_k <<<HD*Dm /1024, 256>>>(wo, woh, wol);
    conv_single_k<<<En*Dm*Id/1024, 256>>>(wg, wgh);
    conv_single_k<<<En*Dm*Id/1024, 256>>>(wu, wuh);
    conv_single_k<<<En*Id*Dm/1024, 256>>>(wd, wdh);

    // 1. h = rmsnorm(x, ln1) -> hi/lo halves
    rmsnorm_hl_k<<<Sq, 256>>>(x, ln1, hh, hl, Dm);
    // 2. q,k,v projections (split mma, cp.async)
    gemm_mma2<false,false,false,false,true><<<dim3(HD/128,  Sq/128), 256, SM_SPLIT>>>(hh, hl, wqh, wql, pq, nullptr, Sq, HD, Dm);
    gemm_mma2<false,false,false,false,true><<<dim3(KVD/128, Sq/128), 256, SM_SPLIT>>>(hh, hl, wkh, wkl, pk, nullptr, Sq, KVD, Dm);
    gemm_mma2<false,false,false,false,true><<<dim3(KVD/128, Sq/128), 256, SM_SPLIT>>>(hh, hl, wvh, wvl, pv, nullptr, Sq, KVD, Dm);
    // 3. q/k rmsnorm (fp32)
    rmsnorm_k<<<Sq, 256>>>(pq, qn, pq, HD);
    rmsnorm_k<<<Sq, 256>>>(pk, kn, pk, KVD);
    // 4. RoPE + hi/lo emit (q pre-scaled by 1/sqrt(DH)); v convert
    qk_fin_k<<<(Sq*Hn*128)/256, 256>>>(pq, qh, ql, Hn, 0.08838834764831845f);
    qk_fin_k<<<(Sq*KVn*128)/256, 256>>>(pk, kh, kl, KVn, 1.0f);
    conv_split_k<<<Sq*KVD/1024, 256>>>(pv, vh, vl);
    // 5. attention (split mma flash, cp.async) -> o hi/lo
    attn_mma<<<dim3(Sq/128, Hn), 256, ATT_SMEM>>>(out);
    // 6. x1 = x + o @ wo
    gemm_mma2<false,false,false,true,true><<<dim3(Dm/128, Sq/128), 256, SM_SPLIT>>>(oh, ol, woh, wol, out, x, Sq, Dm, HD);
    // 7. t = rmsnorm(x1, ln2) -> fp32 + hi
    rmsnorm_th_k<<<Sq, 256>>>(out, ln2, pt, th, Dm);
    // 8. routing
    reset_k<<<1, 256>>>();
    router_k<<<Sq, 256>>>(pt, rw, rb);
    // 9. expert gate/up (gathered, single mma)
    gemm_mma2<true,false,true,false,false><<<dim3(Id/128, Sq/128, En), 256, SM_SINGLE>>>(th, nullptr, wgh, nullptr, pgate, nullptr, Sq, Id, Dm);
    gemm_mma2<true,false,true,false,false><<<dim3(Id/128, Sq/128, En), 256, SM_SINGLE>>>(th, nullptr, wuh, nullptr, pup, nullptr, Sq, Id, Dm);
    // 10. act -> half
    act_k<<<dim3((Sq*Id)/256, 1, En), 256>>>();
    // 11. down GEMM + weighted scatter
    gemm_mma2<false,true,true,false,false><<<dim3(Dm/128, Sq/128, En), 256, SM_SINGLE>>>(acth, nullptr, wdh, nullptr, nullptr, nullptr, Sq, Dm, Id);
    // 12. out = x1 + moe
    final_add_k<<<(Sq*Dm)/256, 256>>>(out);
}

// round 8
// speedup vs baseline: 4.5118x; 1.0483x over previous
#include <cuda_runtime.h>
#include <cuda_fp16.h>
#include <math.h>
#include <stdint.h>

// ---------------- problem constants ----------------
#define Sq   2048
#define Dm   2048
#define Hn   16
#define KVn  4
#define DHd  128
#define En   8
#define Id   1024
#define HD   2048
#define KVD  512
#define EPSf 1e-6f

// ---------------- static device scratch ----------------
__device__ float g_q   [Sq*HD];
__device__ float g_k   [Sq*KVD];
__device__ float g_v   [Sq*KVD];
__device__ float g_t   [Sq*Dm];
__device__ float g_moe [2*Sq*Dm];
__device__ int   g_cnt [En];
__device__ int   g_ptok[En*Sq];
__device__ float g_pw  [En*Sq];
__device__ int   g_pslot[En*Sq];
// fp16 activations
__device__ __half g_hh [Sq*Dm];
__device__ __half g_hl [Sq*Dm];
__device__ __half g_qh [Sq*HD];
__device__ __half g_ql [Sq*HD];
__device__ __half g_kh2[Sq*KVD];
__device__ __half g_kl2[Sq*KVD];
__device__ __half g_vh [Sq*KVD];
__device__ __half g_vl [Sq*KVD];
__device__ __half g_oh [Sq*HD];
__device__ __half g_ol [Sq*HD];
__device__ __half g_th [Sq*Dm];
__device__ __half g_gateh[En*Sq*Id];
__device__ __half g_uph  [En*Sq*Id];
__device__ __half g_acth [En*Sq*Id];
// fp16 weights
__device__ __half w_qh[Dm*HD];
__device__ __half w_ql[Dm*HD];
__device__ __half w_kh[Dm*KVD];
__device__ __half w_kl[Dm*KVD];
__device__ __half w_vh[Dm*KVD];
__device__ __half w_vl[Dm*KVD];
__device__ __half w_oh[HD*Dm];
__device__ __half w_ol[HD*Dm];
__device__ __half w_gh[En*Dm*Id];
__device__ __half w_uh[En*Dm*Id];
__device__ __half w_dh[En*Id*Dm];

// ---------------- helpers ----------------
__device__ __forceinline__ uint32_t smem_u32(const void* p) {
    uint32_t a;
    asm("{ .reg .u64 t; cvta.to.shared.u64 t, %1; cvt.u32.u64 %0, t; }" : "=r"(a) : "l"(p));
    return a;
}
__device__ __forceinline__ void ldsm4(uint32_t* r, uint32_t a) {
    asm volatile("ldmatrix.sync.aligned.m8n8.x4.shared.b16 {%0,%1,%2,%3}, [%4];"
                 : "=r"(r[0]), "=r"(r[1]), "=r"(r[2]), "=r"(r[3]) : "r"(a));
}
__device__ __forceinline__ void ldsm4t(uint32_t* r, uint32_t a) {
    asm volatile("ldmatrix.sync.aligned.m8n8.x4.trans.shared.b16 {%0,%1,%2,%3}, [%4];"
                 : "=r"(r[0]), "=r"(r[1]), "=r"(r[2]), "=r"(r[3]) : "r"(a));
}
__device__ __forceinline__ void mma16816(float* d, const uint32_t* a, const uint32_t* b) {
    asm volatile("mma.sync.aligned.m16n8k16.row.col.f32.f16.f16.f32 "
                 "{%0,%1,%2,%3}, {%4,%5,%6,%7}, {%8,%9}, {%0,%1,%2,%3};"
                 : "+f"(d[0]), "+f"(d[1]), "+f"(d[2]), "+f"(d[3])
                 : "r"(a[0]), "r"(a[1]), "r"(a[2]), "r"(a[3]), "r"(b[0]), "r"(b[1]));
}
__device__ __forceinline__ void split2(float x, float y, half2& hi, half2& lo) {
    hi = __floats2half2_rn(x, y);
    lo = __floats2half2_rn(x - __low2float(hi), y - __high2float(hi));
}
#define CP16(dst, src) \
    asm volatile("cp.async.cg.shared.global [%0], [%1], 16;" :: "r"((uint32_t)(dst)), "l"(src))
#define CP_COMMIT() asm volatile("cp.async.commit_group;" ::: "memory")
#define CP_WAIT(n)  asm volatile("cp.async.wait_group %0;" :: "n"(n) : "memory")

// ---------------- weight/activation converts ----------------
__global__ __launch_bounds__(256) void conv_split_k(const float* __restrict__ s,
                                                    __half* __restrict__ hi,
                                                    __half* __restrict__ lo) {
    size_t i = ((size_t)blockIdx.x * 256 + threadIdx.x) * 4;
    float4 v = *(const float4*)(s + i);
    half2 h0, l0, h1, l1;
    split2(v.x, v.y, h0, l0); split2(v.z, v.w, h1, l1);
    *(half2*)(hi + i) = h0; *(half2*)(hi + i + 2) = h1;
    *(half2*)(lo + i) = l0; *(half2*)(lo + i + 2) = l1;
}
__global__ __launch_bounds__(256) void conv_single_k(const float* __restrict__ s,
                                                     __half* __restrict__ hi) {
    size_t i = ((size_t)blockIdx.x * 256 + threadIdx.x) * 4;
    float4 v = *(const float4*)(s + i);
    *(half2*)(hi + i)     = __floats2half2_rn(v.x, v.y);
    *(half2*)(hi + i + 2) = __floats2half2_rn(v.z, v.w);
}

// ================= fp16 mma GEMM, cp.async double-buffered =================
#define AT_SZ 10240     // 128 rows x 80B
#define BT_SZ 8704      // 32 rows x 272B
#define SM_SPLIT  (2048 + 2*(2*AT_SZ + 2*BT_SZ))   // 77824
#define SM_SINGLE (2048 + 2*(AT_SZ + BT_SZ))       // 39936

template<bool GATHER, bool SCATTER, bool EXPERT, bool RES, bool SPLIT, bool OUTH>
__global__ __launch_bounds__(256, 2) void gemm_mma2(
    const __half* __restrict__ Ah, const __half* __restrict__ Al,
    const __half* __restrict__ Bh, const __half* __restrict__ Bl,
    void* __restrict__ Cv, const float* __restrict__ res,
    int M, int N, int K)
{
    extern __shared__ char smem[];
    const int tid = threadIdx.x, lane = tid & 31, wid = tid >> 5;
    const int wm = wid & 3, wn = wid >> 2;
    const int STG  = SPLIT ? (2 * AT_SZ + 2 * BT_SZ) : (AT_SZ + BT_SZ);
    const int BOFF = SPLIT ? 2 * AT_SZ : AT_SZ;

    int e = 0, cnt = M;
    const __half* Ahe = Ah;
    const __half* Bhe = Bh;
    const __half* Ble = Bl;
    float*  Cf = (float*)Cv;
    __half* Ch = (__half*)Cv;
    if (EXPERT) {
        e = blockIdx.z;
        cnt = g_cnt[e];
        Bhe = Bh + (size_t)e * K * N;
        if (SPLIT) Ble = Bl + (size_t)e * K * N;
        if (!GATHER) Ahe = Ah + (size_t)e * Sq * K;
        if (!SCATTER) { Cf = (float*)Cv + (size_t)e * Sq * N; Ch = (__half*)Cv + (size_t)e * Sq * N; }
    }
    const int m0 = blockIdx.y * 128;
    if (EXPERT && m0 >= cnt) return;
    const int n0 = blockIdx.x * 128;

    int*   stok = (int*)smem;
    float* swt  = (float*)(smem + 512);
    int*   ssl  = (int*)(smem + 1024);
    if (GATHER || SCATTER) {
        if (tid < 128) {
            int r = m0 + tid;
            bool ok = r < cnt;
            stok[tid] = ok ? g_ptok[e * Sq + r] : 0;
            if (SCATTER) {
                swt[tid] = ok ? g_pw[e * Sq + r] : 0.f;
                ssl[tid] = ok ? g_pslot[e * Sq + r] : 0;
            }
        }
        __syncthreads();
    }
    const uint32_t sb = smem_u32(smem);
    const uint32_t tb = sb + 2048;
    const int T = K / 32;

#define ISSUE(it) do { \
        int _k0 = (it) * 32; \
        uint32_t _s0 = tb + ((it) & 1) * STG; \
        _Pragma("unroll") \
        for (int _j = 0; _j < 2; _j++) { \
            int _idx = tid + _j * 256; \
            int _row = _idx >> 2, _c = _idx & 3; \
            int _gr = GATHER ? stok[_row] : (m0 + _row); \
            CP16(_s0 + _row * 80 + _c * 16, Ahe + (size_t)_gr * K + _k0 + _c * 8); \
            if (SPLIT) CP16(_s0 + AT_SZ + _row * 80 + _c * 16, Al + (size_t)_gr * K + _k0 + _c * 8); \
        } \
        _Pragma("unroll") \
        for (int _j = 0; _j < 2; _j++) { \
            int _idx = tid + _j * 256; \
            int _row = _idx >> 4, _c = _idx & 15; \
            CP16(_s0 + BOFF + _row * 272 + _c * 16, Bhe + (size_t)(_k0 + _row) * N + n0 + _c * 8); \
            if (SPLIT) CP16(_s0 + BOFF + BT_SZ + _row * 272 + _c * 16, \
                            Ble + (size_t)(_k0 + _row) * N + n0 + _c * 8); \
        } \
        CP_COMMIT(); \
    } while (0)

    ISSUE(0);
    float acc[2][8][4] = {};
    for (int it = 0; it < T; ++it) {
        if (it + 1 < T) { ISSUE(it + 1); CP_WAIT(1); }
        else            { CP_WAIT(0); }
        __syncthreads();
        uint32_t s0 = tb + (it & 1) * STG;
#pragma unroll
        for (int ks = 0; ks < 2; ks++) {
            uint32_t ah[2][4], al[2][4], bh[8][2], bl[8][2];
            int am = wm * 32 + (lane & 7) + ((lane >> 3) & 1) * 8;
            int ak = ks * 16 + (lane >> 4) * 8;
            uint32_t ab = s0 + am * 80 + ak * 2;
            ldsm4(ah[0], ab);
            ldsm4(ah[1], ab + 16 * 80);
            if (SPLIT) { ldsm4(al[0], ab + AT_SZ); ldsm4(al[1], ab + AT_SZ + 16 * 80); }
            int bk = ks * 16 + (lane & 7) + ((lane >> 3) & 1) * 8;
            int bn = wn * 64 + (lane >> 4) * 8;
            uint32_t bb = s0 + BOFF + bk * 272 + bn * 2;
#pragma unroll
            for (int t = 0; t < 4; t++) {
                uint32_t rr[4];
                ldsm4t(rr, bb + t * 32);
                bh[2 * t][0] = rr[0]; bh[2 * t][1] = rr[1];
                bh[2 * t + 1][0] = rr[2]; bh[2 * t + 1][1] = rr[3];
                if (SPLIT) {
                    ldsm4t(rr, bb + BT_SZ + t * 32);
                    bl[2 * t][0] = rr[0]; bl[2 * t][1] = rr[1];
                    bl[2 * t + 1][0] = rr[2]; bl[2 * t + 1][1] = rr[3];
                }
            }
#pragma unroll
            for (int mt = 0; mt < 2; mt++)
#pragma unroll
                for (int nt = 0; nt < 8; nt++) {
                    mma16816(acc[mt][nt], ah[mt], bh[nt]);
                    if (SPLIT) {
                        mma16816(acc[mt][nt], ah[mt], bl[nt]);
                        mma16816(acc[mt][nt], al[mt], bh[nt]);
                    }
                }
        }
        __syncthreads();
    }
#undef ISSUE

    const int g = lane >> 2, tig = lane & 3;
#pragma unroll
    for (int mt = 0; mt < 2; mt++) {
#pragma unroll
        for (int hh = 0; hh < 2; hh++) {
            int row = wm * 32 + mt * 16 + g + hh * 8;
            if (EXPERT && m0 + row >= cnt) continue;
            if (SCATTER) {
                int token = stok[row]; float w = swt[row]; int slot = ssl[row];
                float* dst = g_moe + ((size_t)slot * Sq + token) * Dm + n0;
#pragma unroll
                for (int nt = 0; nt < 8; nt++) {
                    int c = wn * 64 + nt * 8 + tig * 2;
                    *(float2*)(dst + c) =
                        make_float2(w * acc[mt][nt][2 * hh], w * acc[mt][nt][2 * hh + 1]);
                }
            } else if (OUTH) {
                __half* dst = Ch + (size_t)(m0 + row) * N + n0;
#pragma unroll
                for (int nt = 0; nt < 8; nt++) {
                    int c = wn * 64 + nt * 8 + tig * 2;
                    *(half2*)(dst + c) =
                        __floats2half2_rn(acc[mt][nt][2 * hh], acc[mt][nt][2 * hh + 1]);
                }
            } else {
                float* dst = Cf + (size_t)(m0 + row) * N + n0;
                const float* rs = RES ? (res + (size_t)(m0 + row) * N + n0) : nullptr;
#pragma unroll
                for (int nt = 0; nt < 8; nt++) {
                    int c = wn * 64 + nt * 8 + tig * 2;
                    float2 v = make_float2(acc[mt][nt][2 * hh], acc[mt][nt][2 * hh + 1]);
                    if (RES) { v.x += rs[c]; v.y += rs[c + 1]; }
                    *(float2*)(dst + c) = v;
                }
            }
        }
    }
}

// ================= flash attention: 64-row q blocks, K/V double-buffered =================
// smem layout (bytes):
//   QH 0, QL 17408
//   buf b (b=0,1) at 34816 + b*69632: KH +0, KL +17408, VH +34816, VL +52224
//   PH 174080, PL 183296 (64 x 72 halves)
//   maxb 192512 (4x64 f32), sumb 193536, Mrow 194560, Lrow 194816
#define ATT_SMEM 195072

__global__ __launch_bounds__(256) void attn_mma() {
    extern __shared__ char smem[];
    const uint32_t sb = smem_u32(smem);
    const int qb = gridDim.x - 1 - blockIdx.x;
    const int h = blockIdx.y, kvh = h >> 2;
    const int tid = threadIdx.x, lane = tid & 31, wid = tid >> 5;
    const int wm = wid & 1, wn = wid >> 1;
    float* maxb = (float*)(smem + 192512);
    float* sumb = (float*)(smem + 193536);
    float* Mrow = (float*)(smem + 194560);
    float* Lrow = (float*)(smem + 194816);

    // ---- stage Q hi/lo (pre-scaled): 64 rows x 256B x 2 arrays = 2048 chunks ----
#pragma unroll
    for (int j = 0; j < 8; j++) {
        int idx = tid + j * 256;
        int arr = idx >> 10, r = (idx >> 4) & 63, c = idx & 15;
        const __half* src = (arr ? g_ql : g_qh) + (size_t)(qb * 64 + r) * HD + h * DHd + c * 8;
        CP16(sb + arr * 17408 + r * 272 + c * 16, src);
    }
    // ---- stage KV(0): 64 rows x 256B x 4 arrays = 4096 chunks ----
#pragma unroll
    for (int j = 0; j < 16; j++) {
        int idx = tid + j * 256;
        int arr = idx >> 10, r = (idx >> 4) & 63, c = idx & 15;
        const __half* s = arr == 0 ? g_kh2 : arr == 1 ? g_kl2 : arr == 2 ? g_vh : g_vl;
        CP16(sb + 34816 + arr * 17408 + r * 272 + c * 16,
             s + (size_t)r * KVD + kvh * DHd + c * 8);
    }
    CP_COMMIT();
    if (tid < 64) { Mrow[tid] = -INFINITY; Lrow[tid] = 0.f; }

    float oacc[2][4][4] = {};
    const int g = lane >> 2, tig = lane & 3;
    const int arow = wm * 32 + (lane & 7) + ((lane >> 3) & 1) * 8;
    const int brow16 = wn * 16 + (lane & 7) + 8 * (lane >> 4);

    for (int t = 0; t <= qb; t++) {
        const uint32_t B = sb + 34816 + (uint32_t)(t & 1) * 69632;
        if (t < qb) {
            uint32_t B1 = sb + 34816 + (uint32_t)((t + 1) & 1) * 69632;
#pragma unroll
            for (int j = 0; j < 16; j++) {
                int idx = tid + j * 256;
                int arr = idx >> 10, r = (idx >> 4) & 63, c = idx & 15;
                const __half* s = arr == 0 ? g_kh2 : arr == 1 ? g_kl2 : arr == 2 ? g_vh : g_vl;
                CP16(B1 + arr * 17408 + r * 272 + c * 16,
                     s + (size_t)((t + 1) * 64 + r) * KVD + kvh * DHd + c * 8);
            }
            CP_COMMIT();
            CP_WAIT(1);
        } else {
            CP_WAIT(0);
        }
        __syncthreads();

        // ---- S = Q @ K^T (split) : 64 q rows x 64 kv cols ----
        float sacc[2][2][4] = {};
#pragma unroll
        for (int ks = 0; ks < 8; ks++) {
            uint32_t ah[2][4], al[2][4], bh[2][2], bl[2][2];
            int ak = ks * 16 + (lane >> 4) * 8;
            uint32_t ab = sb + (arow * 136 + ak) * 2;
            ldsm4(ah[0], ab);
            ldsm4(ah[1], ab + 16 * 272);
            ldsm4(al[0], ab + 17408);
            ldsm4(al[1], ab + 17408 + 16 * 272);
            int bk = ks * 16 + ((lane >> 3) & 1) * 8;
            uint32_t bb = B + (brow16 * 136 + bk) * 2;
            {
                uint32_t rr[4];
                ldsm4(rr, bb);
                bh[0][0] = rr[0]; bh[0][1] = rr[1];
                bh[1][0] = rr[2]; bh[1][1] = rr[3];
                ldsm4(rr, bb + 17408);
                bl[0][0] = rr[0]; bl[0][1] = rr[1];
                bl[1][0] = rr[2]; bl[1][1] = rr[3];
            }
#pragma unroll
            for (int mt = 0; mt < 2; mt++)
#pragma unroll
                for (int nf = 0; nf < 2; nf++) {
                    mma16816(sacc[mt][nf], ah[mt], bh[nf]);
                    mma16816(sacc[mt][nf], ah[mt], bl[nf]);
                    mma16816(sacc[mt][nf], al[mt], bh[nf]);
                }
        }

        // ---- causal mask (diagonal tile only) ----
        if (t == qb) {
#pragma unroll
            for (int mt = 0; mt < 2; mt++)
#pragma unroll
                for (int nf = 0; nf < 2; nf++)
#pragma unroll
                    for (int i = 0; i < 4; i++) {
                        int row = wm * 32 + mt * 16 + g + (i >= 2 ? 8 : 0);
                        int col = wn * 16 + nf * 8 + tig * 2 + (i & 1);
                        if (col > row) sacc[mt][nf][i] = -INFINITY;
                    }
        }

        // ---- per-warp row max over its 16 cols ----
        float rmax[2][2];
#pragma unroll
        for (int mt = 0; mt < 2; mt++)
#pragma unroll
            for (int hh = 0; hh < 2; hh++) {
                float m = fmaxf(fmaxf(sacc[mt][0][2 * hh], sacc[mt][0][2 * hh + 1]),
                                fmaxf(sacc[mt][1][2 * hh], sacc[mt][1][2 * hh + 1]));
                m = fmaxf(m, __shfl_xor_sync(0xffffffffu, m, 1));
                m = fmaxf(m, __shfl_xor_sync(0xffffffffu, m, 2));
                rmax[mt][hh] = m;
            }
        if (tig == 0) {
#pragma unroll
            for (int mt = 0; mt < 2; mt++) {
                int r = wm * 32 + mt * 16 + g;
                maxb[wn * 64 + r] = rmax[mt][0];
                maxb[wn * 64 + r + 8] = rmax[mt][1];
            }
        }
        __syncthreads();

        // ---- mnew/alpha, exp, P store (hi/lo), row sums ----
        float alpha[2][2], mnew[2][2], rsum[2][2];
#pragma unroll
        for (int mt = 0; mt < 2; mt++)
#pragma unroll
            for (int hh = 0; hh < 2; hh++) {
                int r = wm * 32 + mt * 16 + g + hh * 8;
                float mo = Mrow[r];
                float mn = fmaxf(fmaxf(mo, maxb[r]),
                                 fmaxf(fmaxf(maxb[64 + r], maxb[128 + r]), maxb[192 + r]));
                mnew[mt][hh] = mn;
                alpha[mt][hh] = expf(mo - mn);
                rsum[mt][hh] = 0.f;
            }
#pragma unroll
        for (int mt = 0; mt < 2; mt++)
#pragma unroll
            for (int nf = 0; nf < 2; nf++)
#pragma unroll
                for (int hh = 0; hh < 2; hh++) {
                    float p0 = expf(sacc[mt][nf][2 * hh]     - mnew[mt][hh]);
                    float p1 = expf(sacc[mt][nf][2 * hh + 1] - mnew[mt][hh]);
                    rsum[mt][hh] += p0 + p1;
                    half2 hi, lo;
                    split2(p0, p1, hi, lo);
                    int r = wm * 32 + mt * 16 + g + hh * 8;
                    int c = wn * 16 + nf * 8 + tig * 2;
                    *(half2*)(smem + 174080 + (r * 72 + c) * 2) = hi;
                    *(half2*)(smem + 183296 + (r * 72 + c) * 2) = lo;
                }
#pragma unroll
        for (int mt = 0; mt < 2; mt++)
#pragma unroll
            for (int hh = 0; hh < 2; hh++) {
                float s = rsum[mt][hh];
                s += __shfl_xor_sync(0xffffffffu, s, 1);
                s += __shfl_xor_sync(0xffffffffu, s, 2);
                rsum[mt][hh] = s;
            }
        if (tig == 0) {
#pragma unroll
            for (int mt = 0; mt < 2; mt++) {
                int r = wm * 32 + mt * 16 + g;
                sumb[wn * 64 + r] = rsum[mt][0];
                sumb[wn * 64 + r + 8] = rsum[mt][1];
            }
        }
        // rescale O accumulators
#pragma unroll
        for (int mt = 0; mt < 2; mt++)
#pragma unroll
            for (int vf = 0; vf < 4; vf++) {
                oacc[mt][vf][0] *= alpha[mt][0]; oacc[mt][vf][1] *= alpha[mt][0];
                oacc[mt][vf][2] *= alpha[mt][1]; oacc[mt][vf][3] *= alpha[mt][1];
            }
        __syncthreads();

        if (wn == 0 && tig == 0) {
#pragma unroll
            for (int mt = 0; mt < 2; mt++)
#pragma unroll
                for (int hh = 0; hh < 2; hh++) {
                    int r = wm * 32 + mt * 16 + g + hh * 8;
                    Lrow[r] = Lrow[r] * alpha[mt][hh]
                              + sumb[r] + sumb[64 + r] + sumb[128 + r] + sumb[192 + r];
                    Mrow[r] = mnew[mt][hh];
                }
        }

        // ---- O += P @ V (split) : 64 x 128, k=64 ----
#pragma unroll
        for (int ks = 0; ks < 4; ks++) {
            uint32_t ph[2][4], pl[2][4], vh[4][2], vl[4][2];
            int ak = ks * 16 + (lane >> 4) * 8;
            uint32_t ab = sb + 174080 + (arow * 72 + ak) * 2;
            ldsm4(ph[0], ab);
            ldsm4(ph[1], ab + 16 * 144);
            ldsm4(pl[0], ab + 9216);
            ldsm4(pl[1], ab + 9216 + 16 * 144);
            int vk = ks * 16 + (lane & 7) + ((lane >> 3) & 1) * 8;
            int vn = wn * 32 + (lane >> 4) * 8;
            uint32_t vb = B + 34816 + (vk * 136 + vn) * 2;
#pragma unroll
            for (int ntp = 0; ntp < 2; ntp++) {
                uint32_t rr[4];
                ldsm4t(rr, vb + ntp * 32);
                vh[2 * ntp][0] = rr[0]; vh[2 * ntp][1] = rr[1];
                vh[2 * ntp + 1][0] = rr[2]; vh[2 * ntp + 1][1] = rr[3];
                ldsm4t(rr, vb + 17408 + ntp * 32);
                vl[2 * ntp][0] = rr[0]; vl[2 * ntp][1] = rr[1];
                vl[2 * ntp + 1][0] = rr[2]; vl[2 * ntp + 1][1] = rr[3];
            }
#pragma unroll
            for (int mt = 0; mt < 2; mt++)
#pragma unroll
                for (int vf = 0; vf < 4; vf++) {
                    mma16816(oacc[mt][vf], ph[mt], vh[vf]);
                    mma16816(oacc[mt][vf], ph[mt], vl[vf]);
                    mma16816(oacc[mt][vf], pl[mt], vh[vf]);
                }
        }
        __syncthreads();
    }

    // ---- epilogue -> o hi/lo ----
#pragma unroll
    for (int mt = 0; mt < 2; mt++)
#pragma unroll
        for (int hh = 0; hh < 2; hh++) {
            int r = wm * 32 + mt * 16 + g + hh * 8;
            float inv = 1.f / Lrow[r];
#pragma unroll
            for (int vf = 0; vf < 4; vf++) {
                int c = wn * 32 + vf * 8 + tig * 2;
                float vx = oacc[mt][vf][2 * hh] * inv;
                float vy = oacc[mt][vf][2 * hh + 1] * inv;
                half2 hi, lo;
                split2(vx, vy, hi, lo);
                size_t dst = (size_t)(qb * 64 + r) * HD + h * DHd + c;
                *(half2*)&g_oh[dst] = hi;
                *(half2*)&g_ol[dst] = lo;
            }
        }
}

// ---------------- rmsnorm variants ----------------
__global__ __launch_bounds__(256) void rmsnorm_k(const float* __restrict__ in,
                                                 const float* __restrict__ w,
                                                 float* __restrict__ out, int cols) {
    int row = blockIdx.x;
    const float* r = in + (size_t)row * cols;
    float ss = 0.f;
    for (int i = threadIdx.x; i < cols; i += 256) { float v = r[i]; ss += v * v; }
    __shared__ float red[256];
    red[threadIdx.x] = ss; __syncthreads();
    for (int st = 128; st > 0; st >>= 1) {
        if (threadIdx.x < st) red[threadIdx.x] += red[threadIdx.x + st];
        __syncthreads();
    }
    float scale = rsqrtf(red[0] / (float)cols + EPSf);
    for (int i = threadIdx.x; i < cols; i += 256)
        out[(size_t)row * cols + i] = r[i] * scale * w[i];
}

__global__ __launch_bounds__(256) void rmsnorm_hl_k(const float* __restrict__ in,
                                                    const float* __restrict__ w,
                                                    __half* __restrict__ ohi,
                                                    __half* __restrict__ olo, int cols) {
    int row = blockIdx.x;
    const float* r = in + (size_t)row * cols;
    float ss = 0.f;
    for (int i = threadIdx.x; i < cols; i += 256) { float v = r[i]; ss += v * v; }
    __shared__ float red[256];
    red[threadIdx.x] = ss; __syncthreads();
    for (int st = 128; st > 0; st >>= 1) {
        if (threadIdx.x < st) red[threadIdx.x] += red[threadIdx.x + st];
        __syncthreads();
    }
    float scale = rsqrtf(red[0] / (float)cols + EPSf);
    for (int i = threadIdx.x; i < cols; i += 256) {
        float val = r[i] * scale * w[i];
        __half hv = __float2half_rn(val);
        ohi[(size_t)row * cols + i] = hv;
        olo[(size_t)row * cols + i] = __float2half_rn(val - __half2float(hv));
    }
}

__global__ __launch_bounds__(256) void rmsnorm_th_k(const float* __restrict__ in,
                                                    const float* __restrict__ w,
                                                    float* __restrict__ out,
                                                    __half* __restrict__ ohi, int cols) {
    int row = blockIdx.x;
    const float* r = in + (size_t)row * cols;
    float ss = 0.f;
    for (int i = threadIdx.x; i < cols; i += 256) { float v = r[i]; ss += v * v; }
    __shared__ float red[256];
    red[threadIdx.x] = ss; __syncthreads();
    for (int st = 128; st > 0; st >>= 1) {
        if (threadIdx.x < st) red[threadIdx.x] += red[threadIdx.x + st];
        __syncthreads();
    }
    float scale = rsqrtf(red[0] / (float)cols + EPSf);
    for (int i = threadIdx.x; i < cols; i += 256) {
        float val = r[i] * scale * w[i];
        out[(size_t)row * cols + i] = val;
        ohi[(size_t)row * cols + i] = __float2half_rn(val);
    }
}

// ---------------- RoPE + hi/lo emit (q scaled) ----------------
__global__ __launch_bounds__(256) void qk_fin_k(const float* __restrict__ src,
                                                __half* __restrict__ hi,
                                                __half* __restrict__ lo,
                                                int nheads, float scale) {
    int idx = blockIdx.x * 256 + threadIdx.x;
    int d = idx & 127;
    int rest = idx >> 7;
    int h = rest % nheads;
    int s = rest / nheads;
    const float* base = src + (size_t)s * (nheads * DHd) + h * DHd;
    float val;
    if (d < 32) {
        float inv = powf(1.0e6f, -(float)d / 32.f);
        float a = (float)s * inv;
        val = base[d] * cosf(a) - base[d + 32] * sinf(a);
    } else if (d < 64) {
        int p = d - 32;
        float inv = powf(1.0e6f, -(float)p / 32.f);
        float a = (float)s * inv;
        val = base[d] * cosf(a) + base[d - 32] * sinf(a);
    } else {
        val = base[d];
    }
    val *= scale;
    __half hv = __float2half_rn(val);
    hi[idx] = hv;
    lo[idx] = __float2half_rn(val - __half2float(hv));
}

// ---------------- router ----------------
__global__ __launch_bounds__(256) void reset_k() {
    if (threadIdx.x < En) g_cnt[threadIdx.x] = 0;
}

__global__ __launch_bounds__(256) void router_k(const float* __restrict__ Tm,
                                                const float* __restrict__ rw,
                                                const float* __restrict__ rb) {
    int row = blockIdx.x, tid = threadIdx.x;
    const float* r = Tm + (size_t)row * Dm;
    float loc[En] = {};
    for (int d = tid; d < Dm; d += 256) {
        float x = r[d];
#pragma unroll
        for (int e = 0; e < En; e++) loc[e] += x * rw[d * En + e];
    }
    __shared__ float sred[256 * En];
#pragma unroll
    for (int e = 0; e < En; e++) sred[tid * En + e] = loc[e];
    __syncthreads();
    for (int st = 128; st > 0; st >>= 1) {
        if (tid < st)
#pragma unroll
            for (int e = 0; e < En; e++) sred[tid * En + e] += sred[(tid + st) * En + e];
        __syncthreads();
    }
    if (tid == 0) {
        float sig[En], scv[En];
#pragma unroll
        for (int e = 0; e < En; e++) {
            float l = sred[e];
            sig[e] = 1.f / (1.f + expf(-l));
            scv[e] = sig[e] + rb[e];
        }
        int i0 = 0;
#pragma unroll
        for (int e = 1; e < En; e++) if (scv[e] > scv[i0]) i0 = e;
        int i1 = -1;
#pragma unroll
        for (int e = 0; e < En; e++)
            if (e != i0 && (i1 < 0 || scv[e] > scv[i1])) i1 = e;
        float a0 = sig[i0], a1 = sig[i1], s = a0 + a1;
        float w0 = a0 / s, w1 = a1 / s;
        int p = atomicAdd(&g_cnt[i0], 1);
        g_ptok[i0 * Sq + p] = row; g_pw[i0 * Sq + p] = w0; g_pslot[i0 * Sq + p] = 0;
        p = atomicAdd(&g_cnt[i1], 1);
        g_ptok[i1 * Sq + p] = row; g_pw[i1 * Sq + p] = w1; g_pslot[i1 * Sq + p] = 1;
    }
}

// ---------------- act = silu(gate)*up (half in/out, 8 elems/thread) ----------------
__global__ __launch_bounds__(256) void act_k() {
    int e = blockIdx.z;
    int cnt = g_cnt[e];
    int i = (blockIdx.x * 256 + threadIdx.x) * 8;
    int row = i >> 10;
    if (row >= cnt) return;
    size_t idx = (size_t)e * Sq * Id + i;
#pragma unroll
    for (int j = 0; j < 4; j++) {
        half2 gh = *(half2*)(g_gateh + idx + 2 * j);
        half2 uh = *(half2*)(g_uph + idx + 2 * j);
        float g0 = __low2float(gh), g1 = __high2float(gh);
        float u0 = __low2float(uh), u1 = __high2float(uh);
        float a0 = (g0 / (1.f + expf(-g0))) * u0;
        float a1 = (g1 / (1.f + expf(-g1))) * u1;
        *(half2*)(g_acth + idx + 2 * j) = __floats2half2_rn(a0, a1);
    }
}

// ---------------- final: out = x1 + moe0 + moe1 (float4) ----------------
__global__ __launch_bounds__(256) void final_add_k(float* __restrict__ out) {
    int i = (blockIdx.x * 256 + threadIdx.x) * 4;
    float4 a = *(float4*)(out + i);
    float4 b = *(float4*)(g_moe + i);
    float4 c = *(float4*)(g_moe + (size_t)Sq * Dm + i);
    a.x += b.x + c.x; a.y += b.y + c.y; a.z += b.z + c.z; a.w += b.w + c.w;
    *(float4*)(out + i) = a;
}

// ---------------- host orchestration ----------------
extern "C" void kernel_launch(void* const* d_in, const int* in_sizes, int n_in,
                              void* d_out, int out_size) {
    const float* x    = (const float*)d_in[0];
    const float* ln1  = (const float*)d_in[1];
    const float* ln2  = (const float*)d_in[2];
    const float* wq   = (const float*)d_in[3];
    const float* wk   = (const float*)d_in[4];
    const float* wv   = (const float*)d_in[5];
    const float* wo   = (const float*)d_in[6];
    const float* qn   = (const float*)d_in[7];
    const float* kn   = (const float*)d_in[8];
    const float* rw   = (const float*)d_in[9];
    const float* rb   = (const float*)d_in[10];
    const float* wg   = (const float*)d_in[11];
    const float* wu   = (const float*)d_in[12];
    const float* wd   = (const float*)d_in[13];
    float* out = (float*)d_out;

    float *pq, *pk, *pv, *pt;
    cudaGetSymbolAddress((void**)&pq, g_q);
    cudaGetSymbolAddress((void**)&pk, g_k);
    cudaGetSymbolAddress((void**)&pv, g_v);
    cudaGetSymbolAddress((void**)&pt, g_t);
    __half *hh, *hl, *qh, *ql, *kh, *kl, *vh, *vl, *oh, *ol, *th, *gateh, *uph, *acth;
    cudaGetSymbolAddress((void**)&hh, g_hh);   cudaGetSymbolAddress((void**)&hl, g_hl);
    cudaGetSymbolAddress((void**)&qh, g_qh);   cudaGetSymbolAddress((void**)&ql, g_ql);
    cudaGetSymbolAddress((void**)&kh, g_kh2);  cudaGetSymbolAddress((void**)&kl, g_kl2);
    cudaGetSymbolAddress((void**)&vh, g_vh);   cudaGetSymbolAddress((void**)&vl, g_vl);
    cudaGetSymbolAddress((void**)&oh, g_oh);   cudaGetSymbolAddress((void**)&ol, g_ol);
    cudaGetSymbolAddress((void**)&th, g_th);
    cudaGetSymbolAddress((void**)&gateh, g_gateh);
    cudaGetSymbolAddress((void**)&uph, g_uph);
    cudaGetSymbolAddress((void**)&acth, g_acth);
    __half *wqh, *wql, *wkh, *wkl, *wvh, *wvl, *woh, *wol, *wgh, *wuh, *wdh;
    cudaGetSymbolAddress((void**)&wqh, w_qh); cudaGetSymbolAddress((void**)&wql, w_ql);
    cudaGetSymbolAddress((void**)&wkh, w_kh); cudaGetSymbolAddress((void**)&wkl, w_kl);
    cudaGetSymbolAddress((void**)&wvh, w_vh); cudaGetSymbolAddress((void**)&wvl, w_vl);
    cudaGetSymbolAddress((void**)&woh, w_oh); cudaGetSymbolAddress((void**)&wol, w_ol);
    cudaGetSymbolAddress((void**)&wgh, w_gh); cudaGetSymbolAddress((void**)&wuh, w_uh);
    cudaGetSymbolAddress((void**)&wdh, w_dh);

    cudaFuncSetAttribute(attn_mma, cudaFuncAttributeMaxDynamicSharedMemorySize, ATT_SMEM);
    cudaFuncSetAttribute(gemm_mma2<false,false,false,false,true ,false>, cudaFuncAttributeMaxDynamicSharedMemorySize, SM_SPLIT);
    cudaFuncSetAttribute(gemm_mma2<false,false,false,true ,true ,false>, cudaFuncAttributeMaxDynamicSharedMemorySize, SM_SPLIT);
    cudaFuncSetAttribute(gemm_mma2<true ,false,true ,false,false,true >, cudaFuncAttributeMaxDynamicSharedMemorySize, SM_SINGLE);
    cudaFuncSetAttribute(gemm_mma2<false,true ,true ,false,false,false>, cudaFuncAttributeMaxDynamicSharedMemorySize, SM_SINGLE);

    // 0. weight conversions
    conv_split_k <<<Dm*HD /1024, 256>>>(wq, wqh, wql);
    conv_split_k <<<Dm*KVD/1024, 256>>>(wk, wkh, wkl);
    conv_split_k <<<Dm*KVD/1024, 256>>>(wv, wvh, wvl);
    conv_split_k <<<HD*Dm /1024, 256>>>(wo, woh, wol);
    conv_single_k<<<En*Dm*Id/1024, 256>>>(wg, wgh);
    conv_single_k<<<En*Dm*Id/1024, 256>>>(wu, wuh);
    conv_single_k<<<En*Id*Dm/1024, 256>>>(wd, wdh);

    // 1. h = rmsnorm(x, ln1) -> hi/lo halves
    rmsnorm_hl_k<<<Sq, 256>>>(x, ln1, hh, hl, Dm);
    // 2. q,k,v projections (split mma)
    gemm_mma2<false,false,false,false,true,false><<<dim3(HD/128,  Sq/128), 256, SM_SPLIT>>>(hh, hl, wqh, wql, pq, nullptr, Sq, HD, Dm);
    gemm_mma2<false,false,false,false,true,false><<<dim3(KVD/128, Sq/128), 256, SM_SPLIT>>>(hh, hl, wkh, wkl, pk, nullptr, Sq, KVD, Dm);
    gemm_mma2<false,false,false,false,true,false><<<dim3(KVD/128, Sq/128), 256, SM_SPLIT>>>(hh, hl, wvh, wvl, pv, nullptr, Sq, KVD, Dm);
    // 3. q/k rmsnorm (fp32)
    rmsnorm_k<<<Sq, 256>>>(pq, qn, pq, HD);
    rmsnorm_k<<<Sq, 256>>>(pk, kn, pk, KVD);
    // 4. RoPE + hi/lo emit; v convert
    qk_fin_k<<<(Sq*Hn*128)/256, 256>>>(pq, qh, ql, Hn, 0.08838834764831845f);
    qk_fin_k<<<(Sq*KVn*128)/256, 256>>>(pk, kh, kl, KVn, 1.0f);
    conv_split_k<<<Sq*KVD/1024, 256>>>(pv, vh, vl);
    // 5. attention (64-row q blocks, pipelined KV)
    attn_mma<<<dim3(Sq/64, Hn), 256, ATT_SMEM>>>();
    // 6. x1 = x + o @ wo
    gemm_mma2<false,false,false,true,true,false><<<dim3(Dm/128, Sq/128), 256, SM_SPLIT>>>(oh, ol, woh, wol, out, x, Sq, Dm, HD);
    // 7. t = rmsnorm(x1, ln2) -> fp32 + hi
    rmsnorm_th_k<<<Sq, 256>>>(out, ln2, pt, th, Dm);
    // 8. routing
    reset_k<<<1, 256>>>();
    router_k<<<Sq, 256>>>(pt, rw, rb);
    // 9. expert gate/up (gathered, half output)
    gemm_mma2<true,false,true,false,false,true><<<dim3(Id/128, Sq/128, En), 256, SM_SINGLE>>>(th, nullptr, wgh, nullptr, gateh, nullptr, Sq, Id, Dm);
    gemm_mma2<true,false,true,false,false,true><<<dim3(Id/128, Sq/128, En), 256, SM_SINGLE>>>(th, nullptr, wuh, nullptr, uph, nullptr, Sq, Id, Dm);
    // 10. act (half in/out)
    act_k<<<dim3((Sq*Id)/2048, 1, En), 256>>>();
    // 11. down GEMM + weighted scatter
    gemm_mma2<false,true,true,false,false,false><<<dim3(Dm/128, Sq/128, En), 256, SM_SINGLE>>>(acth, nullptr, wdh, nullptr, nullptr, nullptr, Sq, Dm, Id);
    // 12. out = x1 + moe
    final_add_k<<<(Sq*Dm)/1024, 256>>>(out);
}